// round 9
// baseline (speedup 1.0000x reference)
#include <cuda_runtime.h>
#include <cuda_bf16.h>
#include <math.h>

#define NN 50000
#define EE 500000
#define DIN 128
#define HH 256
#define PP 100000
#define MR 50048
#define MT (2*MR)
#define NSB 128
#define CHUNK ((NN + NSB - 1) / NSB)
#define BST 40
#define GSM 122880   // gemm smem: 2 bufs x (A 10240*2 + B 20480*2)

__device__ float g_h [(size_t)MT*HH];
__device__ __nv_bfloat16 g_Ah[(size_t)MT*HH];
__device__ __nv_bfloat16 g_Al[(size_t)MT*HH];
__device__ __nv_bfloat16 g_Ch[(size_t)MT*HH];
__device__ __nv_bfloat16 g_Cl[(size_t)MT*HH];
__device__ __nv_bfloat16 g_Bh[229376];
__device__ __nv_bfloat16 g_Bl[229376];
__device__ int   g_deg[2*NN];
__device__ float g_dinv[2*NN];
__device__ int   g_rowptr[2*(NN+1)];
__device__ int   g_wptr[2*NN];
__device__ int   g_csr[2*EE];
__device__ int   g_bsum[2*NSB];
__device__ int   g_boff[2*NSB];

__device__ __forceinline__ void bsplit(float x, __nv_bfloat16& h, __nv_bfloat16& l) {
    h = __float2bfloat16_rn(x);
    l = __float2bfloat16_rn(x - __bfloat162float(h));
}

#define LDM4(R, A) asm volatile( \
    "ldmatrix.sync.aligned.m8n8.x4.shared.b16 {%0,%1,%2,%3}, [%4];" \
    : "=r"(R[0]),"=r"(R[1]),"=r"(R[2]),"=r"(R[3]) : "r"(A))
#define MMAB(D, A, B0, B1) asm volatile( \
    "mma.sync.aligned.m16n8k16.row.col.f32.bf16.bf16.f32 " \
    "{%0,%1,%2,%3},{%4,%5,%6,%7},{%8,%9},{%0,%1,%2,%3};" \
    : "+f"(D[0]),"+f"(D[1]),"+f"(D[2]),"+f"(D[3]) \
    : "r"(A[0]),"r"(A[1]),"r"(A[2]),"r"(A[3]),"r"(B0),"r"(B1))
#define CPA(D, S) asm volatile( \
    "cp.async.cg.shared.global [%0],[%1],16;" :: "r"(D),"l"(S))

// ---------------- CSR build (gridDim.y = side) ------------------------------
__global__ void k_init_deg(int* deg) {
    int i = blockIdx.x * blockDim.x + threadIdx.x;
    if (i < NN) deg[blockIdx.y * NN + i] = 1;
}
__global__ void k_count(const int* __restrict__ es, const int* __restrict__ et,
                        int* __restrict__ deg) {
    int e = blockIdx.x * blockDim.x + threadIdx.x;
    const int* ei = blockIdx.y ? et : es;
    if (e < EE) atomicAdd(&deg[blockIdx.y * NN + ei[EE + e]], 1);
}
__global__ void k_scan1(const int* __restrict__ deg, int* __restrict__ bsum,
                        float* __restrict__ dinv) {
    const int* d = deg + blockIdx.y * NN;
    float* dv = dinv + blockIdx.y * NN;
    int lo = blockIdx.x * CHUNK, hi = min(lo + CHUNK, NN);
    int s = 0;
    for (int i = lo + threadIdx.x; i < hi; i += 256) {
        int dg = d[i];
        dv[i] = rsqrtf((float)dg);
        s += dg - 1;
    }
    __shared__ int sh[8];
    int lane = threadIdx.x & 31, w = threadIdx.x >> 5;
    #pragma unroll
    for (int o = 16; o > 0; o >>= 1) s += __shfl_down_sync(~0u, s, o);
    if (lane == 0) sh[w] = s;
    __syncthreads();
    if (threadIdx.x == 0) {
        int t = 0;
        #pragma unroll
        for (int j = 0; j < 8; j++) t += sh[j];
        bsum[blockIdx.y * NSB + blockIdx.x] = t;
    }
}
__global__ void k_scan2(const int* __restrict__ bsum, int* __restrict__ boff,
                        int* __restrict__ rowptr) {
    __shared__ int sb[NSB];
    int t = threadIdx.x, side = blockIdx.y;
    int orig = bsum[side * NSB + t];
    sb[t] = orig;
    __syncthreads();
    for (int o = 1; o < NSB; o <<= 1) {
        int v = (t >= o) ? sb[t - o] : 0;
        __syncthreads();
        sb[t] += v;
        __syncthreads();
    }
    boff[side * NSB + t] = sb[t] - orig;
    if (t == 0) rowptr[side * (NN + 1) + NN] = EE;
}
__global__ void k_scan3(const int* __restrict__ deg, const int* __restrict__ boff,
                        int* __restrict__ rowptr, int* __restrict__ wptr) {
    int side = blockIdx.y;
    const int* d = deg + side * NN;
    int* rp = rowptr + side * (NN + 1);
    int* wp = wptr + side * NN;
    int lo = blockIdx.x * CHUNK, hi = min(lo + CHUNK, NN);
    __shared__ int wsum[8];
    __shared__ int srun;
    if (threadIdx.x == 0) srun = boff[side * NSB + blockIdx.x];
    __syncthreads();
    int lane = threadIdx.x & 31, w = threadIdx.x >> 5;
    for (int t0 = lo; t0 < hi; t0 += 256) {
        int i = t0 + threadIdx.x;
        int v = (i < hi) ? d[i] - 1 : 0;
        int incl = v;
        #pragma unroll
        for (int o = 1; o < 32; o <<= 1) {
            int u = __shfl_up_sync(~0u, incl, o);
            if (lane >= o) incl += u;
        }
        if (lane == 31) wsum[w] = incl;
        __syncthreads();
        int woff = 0;
        for (int j = 0; j < w; j++) woff += wsum[j];
        if (i < hi) { int e = srun + woff + incl - v; rp[i] = e; wp[i] = e; }
        __syncthreads();
        if (threadIdx.x == 255) srun += woff + incl;
        __syncthreads();
    }
}
__global__ void k_fill(const int* __restrict__ es, const int* __restrict__ et,
                       int* __restrict__ wptr, int* __restrict__ csr) {
    int e = blockIdx.x * blockDim.x + threadIdx.x;
    const int* ei = blockIdx.y ? et : es;
    if (e < EE) {
        int p = atomicAdd(&wptr[blockIdx.y * NN + ei[EE + e]], 1);
        csr[blockIdx.y * EE + p] = ei[e];
    }
}

// transpose W[K,N] -> Bt[n*K + k], split bf16 hi/lo
__global__ void k_wsplit(const float* __restrict__ W, __nv_bfloat16* __restrict__ th,
                         __nv_bfloat16* __restrict__ tl, int K, int N) {
    __shared__ float sh[32][33];
    int k0 = blockIdx.x * 32, n0 = blockIdx.y * 32;
    int tx = threadIdx.x, ty = threadIdx.y;
    #pragma unroll
    for (int j = 0; j < 4; j++)
        sh[ty + j * 8][tx] = W[(size_t)(k0 + ty + j * 8) * N + n0 + tx];
    __syncthreads();
    #pragma unroll
    for (int j = 0; j < 4; j++) {
        int nn = ty + j * 8;
        float v = sh[tx][nn];
        __nv_bfloat16 h, l;
        bsplit(v, h, l);
        th[(size_t)(n0 + nn) * K + k0 + tx] = h;
        tl[(size_t)(n0 + nn) * K + k0 + tx] = l;
    }
}

// ---------------- agg0: splits of norm-agg of raw x (128 cols) --------------
__global__ __launch_bounds__(256, 4)
void k_aggx(const float* __restrict__ xs, const float* __restrict__ xt,
            const int* __restrict__ rowptr, const int* __restrict__ csr,
            const float* __restrict__ dinv,
            __nv_bfloat16* __restrict__ oh, __nv_bfloat16* __restrict__ ol) {
    int r = blockIdx.x * 8 + threadIdx.y;
    if (r >= MT) return;
    int side = r >= MR;
    int node = r - side * MR;
    int c = threadIdx.x * 4;
    union { __nv_bfloat16 b[4]; uint2 u; } H, L;
    if (node >= NN) {
        H.u = make_uint2(0, 0);
        *(uint2*)(oh + (size_t)r * DIN + c) = H.u;
        *(uint2*)(ol + (size_t)r * DIN + c) = H.u;
        return;
    }
    const float* x = side ? xt : xs;
    const float* dv = dinv + side * NN;
    const int* rp = rowptr + side * (NN + 1);
    const int* cs = csr + side * EE;
    float di = dv[node];
    float4 v = *(const float4*)(x + (size_t)node * DIN + c);
    float w0 = di * di;
    float4 acc = make_float4(v.x*w0, v.y*w0, v.z*w0, v.w*w0);
    int lo = rp[node], hi = rp[node + 1];
    for (int e = lo; e < hi; e++) {
        int s = cs[e];
        float w = di * dv[s];
        float4 u = *(const float4*)(x + (size_t)s * DIN + c);
        acc.x += w*u.x; acc.y += w*u.y; acc.z += w*u.z; acc.w += w*u.w;
    }
    bsplit(acc.x, H.b[0], L.b[0]); bsplit(acc.y, H.b[1], L.b[1]);
    bsplit(acc.z, H.b[2], L.b[2]); bsplit(acc.w, H.b[3], L.b[3]);
    *(uint2*)(oh + (size_t)r * DIN + c) = H.u;
    *(uint2*)(ol + (size_t)r * DIN + c) = L.u;
}

// ---------------- agg1: splits of norm-agg of h (256 cols) ------------------
__global__ __launch_bounds__(256, 4)
void k_aggh(const float* __restrict__ h, const int* __restrict__ rowptr,
            const int* __restrict__ csr, const float* __restrict__ dinv,
            __nv_bfloat16* __restrict__ oh, __nv_bfloat16* __restrict__ ol) {
    int r = blockIdx.x * 4 + threadIdx.y;
    if (r >= MT) return;
    int side = r >= MR;
    int node = r - side * MR;
    int c = threadIdx.x * 4;
    union { __nv_bfloat16 b[4]; uint2 u; } H, L;
    if (node >= NN) {
        H.u = make_uint2(0, 0);
        *(uint2*)(oh + (size_t)r * HH + c) = H.u;
        *(uint2*)(ol + (size_t)r * HH + c) = H.u;
        return;
    }
    const float* dv = dinv + side * NN;
    const int* rp = rowptr + side * (NN + 1);
    const int* cs = csr + side * EE;
    const float* hb = h + (size_t)side * MR * HH;
    float di = dv[node];
    float4 v = *(const float4*)(h + (size_t)r * HH + c);
    float w0 = di * di;
    float4 acc = make_float4(v.x*w0, v.y*w0, v.z*w0, v.w*w0);
    int lo = rp[node], hi = rp[node + 1];
    for (int e = lo; e < hi; e++) {
        int s = cs[e];
        float w = di * dv[s];
        float4 u = *(const float4*)(hb + (size_t)s * HH + c);
        acc.x += w*u.x; acc.y += w*u.y; acc.z += w*u.z; acc.w += w*u.w;
    }
    bsplit(acc.x, H.b[0], L.b[0]); bsplit(acc.y, H.b[1], L.b[1]);
    bsplit(acc.z, H.b[2], L.b[2]); bsplit(acc.w, H.b[3], L.b[3]);
    *(uint2*)(oh + (size_t)r * HH + c) = H.u;
    *(uint2*)(ol + (size_t)r * HH + c) = L.u;
}

// ---------------- bf16x3 GEMM, tile 128x256, 512 threads, 16 warps ----------
// MODE 0: relu(acc+bias) -> fp32; MODE 1: relu(acc+bias) -> bsplit;
// MODE 2: acc -> fp32, B per side.
// smem/buf: Ah@0 10240 | Al@10240 | Bh@20480 20480 | Bl@40960 ; buf stride 61440
template<int MODE>
__global__ __launch_bounds__(512, 1)
void k_gemm_bf(const __nv_bfloat16* __restrict__ Ah, const __nv_bfloat16* __restrict__ Al,
               const __nv_bfloat16* __restrict__ Bth, const __nv_bfloat16* __restrict__ Btl,
               const __nv_bfloat16* __restrict__ B2h, const __nv_bfloat16* __restrict__ B2l,
               const float* __restrict__ bias, float* __restrict__ Cf,
               __nv_bfloat16* __restrict__ Oh, __nv_bfloat16* __restrict__ Ol, int K) {
    extern __shared__ __nv_bfloat16 smem_dyn[];
    unsigned smb = (unsigned)__cvta_generic_to_shared(smem_dyn);
    int tid = threadIdx.x, lane = tid & 31, wid = tid >> 5;
    int wm = wid & 1, wn = wid >> 1;        // 2 x 8 warps, warp tile 64x32
    int rb = blockIdx.x * 128;
    int T = K >> 5;
    const __nv_bfloat16* bsrc_h = (MODE == 2 && rb >= MR) ? B2h : Bth;
    const __nv_bfloat16* bsrc_l = (MODE == 2 && rb >= MR) ? B2l : Btl;

    float acc[4][4][4];
    #pragma unroll
    for (int a = 0; a < 4; a++)
        #pragma unroll
        for (int b = 0; b < 4; b++)
            #pragma unroll
            for (int c = 0; c < 4; c++) acc[a][b][c] = 0.f;

    // A staging: 512 threads, row = tid>>2 (128), q = tid&3 (16B chunk)
    int arw = tid >> 2, aq = tid & 3;
    const __nv_bfloat16* pa = Ah + (size_t)(rb + arw) * K + aq * 8;
    const __nv_bfloat16* pl = Al + (size_t)(rb + arw) * K + aq * 8;
    unsigned sda = (unsigned)((arw * BST + aq * 8) * 2);
    // B staging: row = tid>>1 (256), 2 chunks each
    int brw = tid >> 1, bq = (tid & 1) * 2;
    const __nv_bfloat16* pb = bsrc_h + (size_t)brw * K + bq * 8;
    const __nv_bfloat16* pq = bsrc_l + (size_t)brw * K + bq * 8;
    unsigned sdb = (unsigned)((brw * BST + bq * 8) * 2);

    auto stage = [&](int t, int buf) {
        unsigned o = smb + buf * 61440;
        CPA(o + sda,         pa + t * 32);
        CPA(o + 10240 + sda, pl + t * 32);
        CPA(o + 20480 + sdb,      pb + t * 32);
        CPA(o + 20480 + sdb + 16, pb + t * 32 + 8);
        CPA(o + 40960 + sdb,      pq + t * 32);
        CPA(o + 40960 + sdb + 16, pq + t * 32 + 8);
    };
    stage(0, 0);
    asm volatile("cp.async.commit_group;");

    for (int t = 0; t < T; t++) {
        int buf = t & 1;
        if (t + 1 < T) {
            stage(t + 1, buf ^ 1);
            asm volatile("cp.async.commit_group;");
            asm volatile("cp.async.wait_group 1;");
        } else {
            asm volatile("cp.async.wait_group 0;");
        }
        __syncthreads();
        unsigned pAh = smb + buf * 61440, pAl = pAh + 10240;
        unsigned pBh = pAh + 20480, pBl = pAh + 40960;
        #pragma unroll
        for (int ks = 0; ks < 2; ks++) {
            unsigned ah[4][4], al[4][4], bf[2][4];
            int ach = ks * 2 + (lane >> 4);
            int arow = wm * 64 + (lane & 15);
            #pragma unroll
            for (int mt = 0; mt < 4; mt++) {
                unsigned off = (unsigned)(((arow + mt * 16) * BST + ach * 8) * 2);
                LDM4(ah[mt], pAh + off);
                LDM4(al[mt], pAl + off);
            }
            int bch = ks * 2 + ((lane >> 3) & 1);
            int brow = wn * 32 + (lane & 7) + (lane >> 4) * 8;
            unsigned offb0 = (unsigned)((brow * BST + bch * 8) * 2);
            unsigned offb1 = (unsigned)(((brow + 16) * BST + bch * 8) * 2);
            LDM4(bf[0], pBh + offb0);
            LDM4(bf[1], pBh + offb1);
            #pragma unroll
            for (int mt = 0; mt < 4; mt++)
                #pragma unroll
                for (int nt = 0; nt < 4; nt++)
                    MMAB(acc[mt][nt], ah[mt], bf[nt >> 1][(nt & 1) * 2], bf[nt >> 1][(nt & 1) * 2 + 1]);
            #pragma unroll
            for (int mt = 0; mt < 4; mt++)
                #pragma unroll
                for (int nt = 0; nt < 4; nt++)
                    MMAB(acc[mt][nt], al[mt], bf[nt >> 1][(nt & 1) * 2], bf[nt >> 1][(nt & 1) * 2 + 1]);
            LDM4(bf[0], pBl + offb0);
            LDM4(bf[1], pBl + offb1);
            #pragma unroll
            for (int mt = 0; mt < 4; mt++)
                #pragma unroll
                for (int nt = 0; nt < 4; nt++)
                    MMAB(acc[mt][nt], ah[mt], bf[nt >> 1][(nt & 1) * 2], bf[nt >> 1][(nt & 1) * 2 + 1]);
        }
        __syncthreads();
    }

    int g = lane >> 2, tg = lane & 3;
    #pragma unroll
    for (int mt = 0; mt < 4; mt++) {
        int r0 = rb + wm * 64 + mt * 16 + g;
        #pragma unroll
        for (int nt = 0; nt < 4; nt++) {
            int c = wn * 32 + nt * 8 + tg * 2;
            float2 bv = make_float2(0.f, 0.f);
            if (MODE < 2) bv = *(const float2*)(bias + c);
            #pragma unroll
            for (int hrow = 0; hrow < 2; hrow++) {
                int r = r0 + hrow * 8;
                float v0 = acc[mt][nt][hrow * 2];
                float v1 = acc[mt][nt][hrow * 2 + 1];
                if (MODE < 2) {
                    v0 = fmaxf(v0 + bv.x, 0.f);
                    v1 = fmaxf(v1 + bv.y, 0.f);
                }
                if (MODE == 1) {
                    __nv_bfloat16 h0, l0, h1, l1;
                    bsplit(v0, h0, l0); bsplit(v1, h1, l1);
                    *(__nv_bfloat162*)(Oh + (size_t)r * HH + c) = __nv_bfloat162(h0, h1);
                    *(__nv_bfloat162*)(Ol + (size_t)r * HH + c) = __nv_bfloat162(l0, l1);
                } else {
                    *(float2*)(Cf + (size_t)r * HH + c) = make_float2(v0, v1);
                }
            }
        }
    }
}

// ---------------- pair epilogue ---------------------------------------------
__global__ __launch_bounds__(256)
void k_pair(const float* __restrict__ Z, const int* __restrict__ y,
            const float* __restrict__ fcb, const float* __restrict__ fc2W,
            const float* __restrict__ fc2b, float* __restrict__ out) {
    int w = threadIdx.x >> 5, lane = threadIdx.x & 31;
    int p = blockIdx.x * 8 + w;
    if (p >= PP) return;
    int y0 = y[2*p], y1 = y[2*p+1];
    const float* zl = Z + (size_t)y0 * HH;
    const float* zr = Z + (size_t)(MR + y1) * HH;
    int c = lane * 8;
    float s = 0.f;
    #pragma unroll
    for (int q = 0; q < 2; q++) {
        int cc = c + q * 4;
        float4 a = *(const float4*)(zl + cc);
        float4 b = *(const float4*)(zr + cc);
        float4 fb = *(const float4*)(fcb + cc);
        float4 fw = *(const float4*)(fc2W + cc);
        s += fmaxf(a.x + b.x + fb.x, 0.f) * fw.x;
        s += fmaxf(a.y + b.y + fb.y, 0.f) * fw.y;
        s += fmaxf(a.z + b.z + fb.z, 0.f) * fw.z;
        s += fmaxf(a.w + b.w + fb.w, 0.f) * fw.w;
    }
    #pragma unroll
    for (int o = 16; o > 0; o >>= 1) s += __shfl_xor_sync(~0u, s, o);
    if (lane == 0) out[p] = 1.f / (1.f + expf(-(s + fc2b[0])));
}

// ---------------- launch ----------------------------------------------------
extern "C" void kernel_launch(void* const* d_in, const int* in_sizes, int n_in,
                              void* d_out, int out_size) {
    const float* x_s  = (const float*)d_in[0];
    const float* x_t  = (const float*)d_in[1];
    const int*   ei_s = (const int*)  d_in[2];
    const int*   ei_t = (const int*)  d_in[3];
    const int*   y    = (const int*)  d_in[4];
    const float* W1   = (const float*)d_in[5];
    const float* b1   = (const float*)d_in[6];
    const float* W2   = (const float*)d_in[7];
    const float* b2   = (const float*)d_in[8];
    const float* fcW  = (const float*)d_in[9];
    const float* fcb  = (const float*)d_in[10];
    const float* fc2W = (const float*)d_in[11];
    const float* fc2b = (const float*)d_in[12];
    float* out = (float*)d_out;

    float *h, *dv;
    __nv_bfloat16 *Ah, *Al, *Ch, *Cl, *Bh, *Bl;
    int *deg, *rp, *wp, *cs, *bs, *bo;
    cudaGetSymbolAddress((void**)&h,  g_h);
    cudaGetSymbolAddress((void**)&Ah, g_Ah);
    cudaGetSymbolAddress((void**)&Al, g_Al);
    cudaGetSymbolAddress((void**)&Ch, g_Ch);
    cudaGetSymbolAddress((void**)&Cl, g_Cl);
    cudaGetSymbolAddress((void**)&Bh, g_Bh);
    cudaGetSymbolAddress((void**)&Bl, g_Bl);
    cudaGetSymbolAddress((void**)&dv, g_dinv);
    cudaGetSymbolAddress((void**)&deg, g_deg);
    cudaGetSymbolAddress((void**)&rp, g_rowptr);
    cudaGetSymbolAddress((void**)&wp, g_wptr);
    cudaGetSymbolAddress((void**)&cs, g_csr);
    cudaGetSymbolAddress((void**)&bs, g_bsum);
    cudaGetSymbolAddress((void**)&bo, g_boff);

    cudaFuncSetAttribute(k_gemm_bf<0>, cudaFuncAttributeMaxDynamicSharedMemorySize, GSM);
    cudaFuncSetAttribute(k_gemm_bf<1>, cudaFuncAttributeMaxDynamicSharedMemorySize, GSM);
    cudaFuncSetAttribute(k_gemm_bf<2>, cudaFuncAttributeMaxDynamicSharedMemorySize, GSM);

    // weights: W1t@0, W2t@32768, fcTop@98304, fcBot@163840
    k_wsplit<<<dim3(DIN/32, HH/32), dim3(32,8)>>>(W1, Bh, Bl, DIN, HH);
    k_wsplit<<<dim3(HH/32, HH/32), dim3(32,8)>>>(W2, Bh + 32768, Bl + 32768, HH, HH);
    k_wsplit<<<dim3(HH/32, HH/32), dim3(32,8)>>>(fcW, Bh + 98304, Bl + 98304, HH, HH);
    k_wsplit<<<dim3(HH/32, HH/32), dim3(32,8)>>>(fcW + (size_t)HH * HH, Bh + 163840, Bl + 163840, HH, HH);

    dim3 gn((NN + 255) / 256, 2), ge((EE + 255) / 256, 2);
    k_init_deg<<<gn, 256>>>(deg);
    k_count<<<ge, 256>>>(ei_s, ei_t, deg);
    k_scan1<<<dim3(NSB, 2), 256>>>(deg, bs, dv);
    k_scan2<<<dim3(1, 2), NSB>>>(bs, bo, rp);
    k_scan3<<<dim3(NSB, 2), 256>>>(deg, bo, rp, wp);
    k_fill<<<ge, 256>>>(ei_s, ei_t, wp, cs);

    int gg = MT / 128;
    k_aggx<<<MT / 8, dim3(32, 8)>>>(x_s, x_t, rp, cs, dv, Ah, Al);
    k_gemm_bf<0><<<gg, 512, GSM>>>(Ah, Al, Bh, Bl, Bh, Bl, b1, h, Ah, Al, DIN);
    k_aggh<<<MT / 4, dim3(64, 4)>>>(h, rp, cs, dv, Ch, Cl);
    k_gemm_bf<1><<<gg, 512, GSM>>>(Ch, Cl, Bh + 32768, Bl + 32768, Bh, Bl, b2, h, Ah, Al, HH);
    k_gemm_bf<2><<<gg, 512, GSM>>>(Ah, Al, Bh + 98304, Bl + 98304, Bh + 163840, Bl + 163840,
                                   b2, h, Ah, Al, HH);
    k_pair<<<(PP + 7) / 8, 256>>>(h, y, fcb, fc2W, fc2b, out);
}

// round 10
// speedup vs baseline: 1.0883x; 1.0883x over previous
#include <cuda_runtime.h>
#include <cuda_bf16.h>
#include <math.h>

#define NN 50000
#define EE 500000
#define DIN 128
#define HH 256
#define PP 100000
#define MR 50048
#define MT (2*MR)
#define NSB 128
#define CHUNK ((NN + NSB - 1) / NSB)
#define BST 40

__device__ float g_h [(size_t)MT*HH];
__device__ __nv_bfloat16 g_Ah[(size_t)MT*HH];
__device__ __nv_bfloat16 g_Al[(size_t)MT*HH];
__device__ __nv_bfloat16 g_Ch[(size_t)MT*HH];
__device__ __nv_bfloat16 g_Cl[(size_t)MT*HH];
__device__ __nv_bfloat16 g_Bh[229376];
__device__ __nv_bfloat16 g_Bl[229376];
__device__ int   g_deg[2*NN];
__device__ float g_dinv[2*NN];
__device__ int   g_rowptr[2*(NN+1)];
__device__ int   g_wptr[2*NN];
__device__ int   g_csr[2*EE];
__device__ int   g_bsum[2*NSB];
__device__ int   g_boff[2*NSB];

__device__ __forceinline__ void bsplit(float x, __nv_bfloat16& h, __nv_bfloat16& l) {
    h = __float2bfloat16_rn(x);
    l = __float2bfloat16_rn(x - __bfloat162float(h));
}

#define LDM4(R, A) asm volatile( \
    "ldmatrix.sync.aligned.m8n8.x4.shared.b16 {%0,%1,%2,%3}, [%4];" \
    : "=r"(R[0]),"=r"(R[1]),"=r"(R[2]),"=r"(R[3]) : "r"(A))
#define MMAB(D, A, B0, B1) asm volatile( \
    "mma.sync.aligned.m16n8k16.row.col.f32.bf16.bf16.f32 " \
    "{%0,%1,%2,%3},{%4,%5,%6,%7},{%8,%9},{%0,%1,%2,%3};" \
    : "+f"(D[0]),"+f"(D[1]),"+f"(D[2]),"+f"(D[3]) \
    : "r"(A[0]),"r"(A[1]),"r"(A[2]),"r"(A[3]),"r"(B0),"r"(B1))
#define CPA(D, S) asm volatile( \
    "cp.async.cg.shared.global [%0],[%1],16;" :: "r"(D),"l"(S))

// ---------------- CSR build (gridDim.y = side) ------------------------------
__global__ void k_init_deg(int* deg) {
    int i = blockIdx.x * blockDim.x + threadIdx.x;
    if (i < NN) deg[blockIdx.y * NN + i] = 1;
}
__global__ void k_count(const int* __restrict__ es, const int* __restrict__ et,
                        int* __restrict__ deg) {
    int e = blockIdx.x * blockDim.x + threadIdx.x;
    const int* ei = blockIdx.y ? et : es;
    if (e < EE) atomicAdd(&deg[blockIdx.y * NN + ei[EE + e]], 1);
}
__global__ void k_scan1(const int* __restrict__ deg, int* __restrict__ bsum,
                        float* __restrict__ dinv) {
    const int* d = deg + blockIdx.y * NN;
    float* dv = dinv + blockIdx.y * NN;
    int lo = blockIdx.x * CHUNK, hi = min(lo + CHUNK, NN);
    int s = 0;
    for (int i = lo + threadIdx.x; i < hi; i += 256) {
        int dg = d[i];
        dv[i] = rsqrtf((float)dg);
        s += dg - 1;
    }
    __shared__ int sh[8];
    int lane = threadIdx.x & 31, w = threadIdx.x >> 5;
    #pragma unroll
    for (int o = 16; o > 0; o >>= 1) s += __shfl_down_sync(~0u, s, o);
    if (lane == 0) sh[w] = s;
    __syncthreads();
    if (threadIdx.x == 0) {
        int t = 0;
        #pragma unroll
        for (int j = 0; j < 8; j++) t += sh[j];
        bsum[blockIdx.y * NSB + blockIdx.x] = t;
    }
}
__global__ void k_scan2(const int* __restrict__ bsum, int* __restrict__ boff,
                        int* __restrict__ rowptr) {
    __shared__ int sb[NSB];
    int t = threadIdx.x, side = blockIdx.y;
    int orig = bsum[side * NSB + t];
    sb[t] = orig;
    __syncthreads();
    for (int o = 1; o < NSB; o <<= 1) {
        int v = (t >= o) ? sb[t - o] : 0;
        __syncthreads();
        sb[t] += v;
        __syncthreads();
    }
    boff[side * NSB + t] = sb[t] - orig;
    if (t == 0) rowptr[side * (NN + 1) + NN] = EE;
}
__global__ void k_scan3(const int* __restrict__ deg, const int* __restrict__ boff,
                        int* __restrict__ rowptr, int* __restrict__ wptr) {
    int side = blockIdx.y;
    const int* d = deg + side * NN;
    int* rp = rowptr + side * (NN + 1);
    int* wp = wptr + side * NN;
    int lo = blockIdx.x * CHUNK, hi = min(lo + CHUNK, NN);
    __shared__ int wsum[8];
    __shared__ int srun;
    if (threadIdx.x == 0) srun = boff[side * NSB + blockIdx.x];
    __syncthreads();
    int lane = threadIdx.x & 31, w = threadIdx.x >> 5;
    for (int t0 = lo; t0 < hi; t0 += 256) {
        int i = t0 + threadIdx.x;
        int v = (i < hi) ? d[i] - 1 : 0;
        int incl = v;
        #pragma unroll
        for (int o = 1; o < 32; o <<= 1) {
            int u = __shfl_up_sync(~0u, incl, o);
            if (lane >= o) incl += u;
        }
        if (lane == 31) wsum[w] = incl;
        __syncthreads();
        int woff = 0;
        for (int j = 0; j < w; j++) woff += wsum[j];
        if (i < hi) { int e = srun + woff + incl - v; rp[i] = e; wp[i] = e; }
        __syncthreads();
        if (threadIdx.x == 255) srun += woff + incl;
        __syncthreads();
    }
}
__global__ void k_fill(const int* __restrict__ es, const int* __restrict__ et,
                       int* __restrict__ wptr, int* __restrict__ csr) {
    int e = blockIdx.x * blockDim.x + threadIdx.x;
    const int* ei = blockIdx.y ? et : es;
    if (e < EE) {
        int p = atomicAdd(&wptr[blockIdx.y * NN + ei[EE + e]], 1);
        csr[blockIdx.y * EE + p] = ei[e];
    }
}

// transpose W[K,N] -> Bt[n*K + k], split bf16 hi/lo
__global__ void k_wsplit(const float* __restrict__ W, __nv_bfloat16* __restrict__ th,
                         __nv_bfloat16* __restrict__ tl, int K, int N) {
    __shared__ float sh[32][33];
    int k0 = blockIdx.x * 32, n0 = blockIdx.y * 32;
    int tx = threadIdx.x, ty = threadIdx.y;
    #pragma unroll
    for (int j = 0; j < 4; j++)
        sh[ty + j * 8][tx] = W[(size_t)(k0 + ty + j * 8) * N + n0 + tx];
    __syncthreads();
    #pragma unroll
    for (int j = 0; j < 4; j++) {
        int nn = ty + j * 8;
        float v = sh[tx][nn];
        __nv_bfloat16 h, l;
        bsplit(v, h, l);
        th[(size_t)(n0 + nn) * K + k0 + tx] = h;
        tl[(size_t)(n0 + nn) * K + k0 + tx] = l;
    }
}

// ---------------- agg0: splits of norm-agg of raw x (128 cols) --------------
__global__ __launch_bounds__(256, 4)
void k_aggx(const float* __restrict__ xs, const float* __restrict__ xt,
            const int* __restrict__ rowptr, const int* __restrict__ csr,
            const float* __restrict__ dinv,
            __nv_bfloat16* __restrict__ oh, __nv_bfloat16* __restrict__ ol) {
    int r = blockIdx.x * 8 + threadIdx.y;
    if (r >= MT) return;
    int side = r >= MR;
    int node = r - side * MR;
    int c = threadIdx.x * 4;
    union { __nv_bfloat16 b[4]; uint2 u; } H, L;
    if (node >= NN) {
        H.u = make_uint2(0, 0);
        *(uint2*)(oh + (size_t)r * DIN + c) = H.u;
        *(uint2*)(ol + (size_t)r * DIN + c) = H.u;
        return;
    }
    const float* x = side ? xt : xs;
    const float* dv = dinv + side * NN;
    const int* rp = rowptr + side * (NN + 1);
    const int* cs = csr + side * EE;
    float di = dv[node];
    float4 v = *(const float4*)(x + (size_t)node * DIN + c);
    float w0 = di * di;
    float4 acc = make_float4(v.x*w0, v.y*w0, v.z*w0, v.w*w0);
    int lo = rp[node], hi = rp[node + 1];
    for (int e = lo; e < hi; e++) {
        int s = cs[e];
        float w = di * dv[s];
        float4 u = *(const float4*)(x + (size_t)s * DIN + c);
        acc.x += w*u.x; acc.y += w*u.y; acc.z += w*u.z; acc.w += w*u.w;
    }
    bsplit(acc.x, H.b[0], L.b[0]); bsplit(acc.y, H.b[1], L.b[1]);
    bsplit(acc.z, H.b[2], L.b[2]); bsplit(acc.w, H.b[3], L.b[3]);
    *(uint2*)(oh + (size_t)r * DIN + c) = H.u;
    *(uint2*)(ol + (size_t)r * DIN + c) = L.u;
}

// ---------------- agg1: splits of norm-agg of h (256 cols) ------------------
__global__ __launch_bounds__(256, 4)
void k_aggh(const float* __restrict__ h, const int* __restrict__ rowptr,
            const int* __restrict__ csr, const float* __restrict__ dinv,
            __nv_bfloat16* __restrict__ oh, __nv_bfloat16* __restrict__ ol) {
    int r = blockIdx.x * 4 + threadIdx.y;
    if (r >= MT) return;
    int side = r >= MR;
    int node = r - side * MR;
    int c = threadIdx.x * 4;
    union { __nv_bfloat16 b[4]; uint2 u; } H, L;
    if (node >= NN) {
        H.u = make_uint2(0, 0);
        *(uint2*)(oh + (size_t)r * HH + c) = H.u;
        *(uint2*)(ol + (size_t)r * HH + c) = H.u;
        return;
    }
    const float* dv = dinv + side * NN;
    const int* rp = rowptr + side * (NN + 1);
    const int* cs = csr + side * EE;
    const float* hb = h + (size_t)side * MR * HH;
    float di = dv[node];
    float4 v = *(const float4*)(h + (size_t)r * HH + c);
    float w0 = di * di;
    float4 acc = make_float4(v.x*w0, v.y*w0, v.z*w0, v.w*w0);
    int lo = rp[node], hi = rp[node + 1];
    for (int e = lo; e < hi; e++) {
        int s = cs[e];
        float w = di * dv[s];
        float4 u = *(const float4*)(hb + (size_t)s * HH + c);
        acc.x += w*u.x; acc.y += w*u.y; acc.z += w*u.z; acc.w += w*u.w;
    }
    bsplit(acc.x, H.b[0], L.b[0]); bsplit(acc.y, H.b[1], L.b[1]);
    bsplit(acc.z, H.b[2], L.b[2]); bsplit(acc.w, H.b[3], L.b[3]);
    *(uint2*)(oh + (size_t)r * HH + c) = H.u;
    *(uint2*)(ol + (size_t)r * HH + c) = L.u;
}

// ---------------- bf16x3 GEMM, reg-lean pass ordering, 2 CTAs/SM ------------
// MODE 0: relu(acc+bias) -> fp32; MODE 1: relu(acc+bias) -> bsplit;
// MODE 2: acc -> fp32, B per side (rows >= MR use B2).
template<int MODE>
__global__ __launch_bounds__(256, 2)
void k_gemm_bf(const __nv_bfloat16* __restrict__ Ah, const __nv_bfloat16* __restrict__ Al,
               const __nv_bfloat16* __restrict__ Bth, const __nv_bfloat16* __restrict__ Btl,
               const __nv_bfloat16* __restrict__ B2h, const __nv_bfloat16* __restrict__ B2l,
               const float* __restrict__ bias, float* __restrict__ Cf,
               __nv_bfloat16* __restrict__ Oh, __nv_bfloat16* __restrict__ Ol, int K) {
    extern __shared__ __nv_bfloat16 smem_dyn[];
    unsigned smb = (unsigned)__cvta_generic_to_shared(smem_dyn);
    int tid = threadIdx.x, lane = tid & 31, wid = tid >> 5;
    int wm = wid & 1, wn = wid >> 1;
    int rb = blockIdx.x * 128, cb = blockIdx.y * 128;
    int T = K >> 5;
    const __nv_bfloat16* bh_src = (MODE == 2 && rb >= MR) ? B2h : Bth;
    const __nv_bfloat16* bl_src = (MODE == 2 && rb >= MR) ? B2l : Btl;

    float acc[4][4][4];
    #pragma unroll
    for (int a = 0; a < 4; a++)
        #pragma unroll
        for (int b = 0; b < 4; b++)
            #pragma unroll
            for (int c = 0; c < 4; c++) acc[a][b][c] = 0.f;

    int srow = tid >> 1, half = tid & 1;
    const __nv_bfloat16* pa = Ah + (size_t)(rb + srow) * K + half * 16;
    const __nv_bfloat16* pl = Al + (size_t)(rb + srow) * K + half * 16;
    const __nv_bfloat16* pb = bh_src + (size_t)(cb + srow) * K + half * 16;
    const __nv_bfloat16* pq = bl_src + (size_t)(cb + srow) * K + half * 16;
    unsigned sd = (unsigned)((srow * BST + half * 16) * 2);

    auto stage = [&](int t, int buf) {
        unsigned o = smb + buf * 10240 + sd;
        CPA(o,         pa + t * 32); CPA(o + 16,    pa + t * 32 + 8);
        CPA(o + 20480, pl + t * 32); CPA(o + 20496, pl + t * 32 + 8);
        CPA(o + 40960, pb + t * 32); CPA(o + 40976, pb + t * 32 + 8);
        CPA(o + 61440, pq + t * 32); CPA(o + 61456, pq + t * 32 + 8);
    };

    stage(0, 0);
    asm volatile("cp.async.commit_group;");

    for (int t = 0; t < T; t++) {
        int buf = t & 1;
        if (t + 1 < T) {
            stage(t + 1, buf ^ 1);
            asm volatile("cp.async.commit_group;");
            asm volatile("cp.async.wait_group 1;");
        } else {
            asm volatile("cp.async.wait_group 0;");
        }
        __syncthreads();

        unsigned pAh = smb + buf * 10240;
        unsigned pAl = pAh + 20480;
        unsigned pBh = pAh + 40960;
        unsigned pBl = pAh + 61440;

        #pragma unroll
        for (int ks = 0; ks < 2; ks++) {
            unsigned ah[4][4], bf[2][4], at[4];
            int ach = ks * 2 + (lane >> 4);
            int arow = wm * 64 + (lane & 15);
            #pragma unroll
            for (int mt = 0; mt < 4; mt++)
                LDM4(ah[mt], pAh + (unsigned)(((arow + mt * 16) * BST + ach * 8) * 2));
            int bch = ks * 2 + ((lane >> 3) & 1);
            int brow = wn * 32 + (lane & 7) + (lane >> 4) * 8;
            unsigned offb0 = (unsigned)((brow * BST + bch * 8) * 2);
            unsigned offb1 = (unsigned)(((brow + 16) * BST + bch * 8) * 2);
            // pass 1: hi*hi
            LDM4(bf[0], pBh + offb0);
            LDM4(bf[1], pBh + offb1);
            #pragma unroll
            for (int mt = 0; mt < 4; mt++)
                #pragma unroll
                for (int nt = 0; nt < 4; nt++)
                    MMAB(acc[mt][nt], ah[mt], bf[nt >> 1][(nt & 1) * 2], bf[nt >> 1][(nt & 1) * 2 + 1]);
            // pass 2: lo*hi (A-lo streamed through a 4-reg temp, B-hi resident)
            #pragma unroll
            for (int mt = 0; mt < 4; mt++) {
                LDM4(at, pAl + (unsigned)(((arow + mt * 16) * BST + ach * 8) * 2));
                #pragma unroll
                for (int nt = 0; nt < 4; nt++)
                    MMAB(acc[mt][nt], at, bf[nt >> 1][(nt & 1) * 2], bf[nt >> 1][(nt & 1) * 2 + 1]);
            }
            // pass 3: hi*lo (B-lo overwrites B regs, A-hi resident)
            LDM4(bf[0], pBl + offb0);
            LDM4(bf[1], pBl + offb1);
            #pragma unroll
            for (int mt = 0; mt < 4; mt++)
                #pragma unroll
                for (int nt = 0; nt < 4; nt++)
                    MMAB(acc[mt][nt], ah[mt], bf[nt >> 1][(nt & 1) * 2], bf[nt >> 1][(nt & 1) * 2 + 1]);
        }
        __syncthreads();
    }

    int g = lane >> 2, tg = lane & 3;
    #pragma unroll
    for (int mt = 0; mt < 4; mt++) {
        int r0 = rb + wm * 64 + mt * 16 + g;
        #pragma unroll
        for (int nt = 0; nt < 4; nt++) {
            int c = cb + wn * 32 + nt * 8 + tg * 2;
            float2 bv = make_float2(0.f, 0.f);
            if (MODE < 2) bv = *(const float2*)(bias + c);
            #pragma unroll
            for (int hrow = 0; hrow < 2; hrow++) {
                int r = r0 + hrow * 8;
                float v0 = acc[mt][nt][hrow * 2];
                float v1 = acc[mt][nt][hrow * 2 + 1];
                if (MODE < 2) {
                    v0 = fmaxf(v0 + bv.x, 0.f);
                    v1 = fmaxf(v1 + bv.y, 0.f);
                }
                if (MODE == 1) {
                    __nv_bfloat16 h0, l0, h1, l1;
                    bsplit(v0, h0, l0); bsplit(v1, h1, l1);
                    *(__nv_bfloat162*)(Oh + (size_t)r * HH + c) = __nv_bfloat162(h0, h1);
                    *(__nv_bfloat162*)(Ol + (size_t)r * HH + c) = __nv_bfloat162(l0, l1);
                } else {
                    *(float2*)(Cf + (size_t)r * HH + c) = make_float2(v0, v1);
                }
            }
        }
    }
}

// ---------------- pair epilogue ---------------------------------------------
__global__ __launch_bounds__(256)
void k_pair(const float* __restrict__ Z, const int* __restrict__ y,
            const float* __restrict__ fcb, const float* __restrict__ fc2W,
            const float* __restrict__ fc2b, float* __restrict__ out) {
    int w = threadIdx.x >> 5, lane = threadIdx.x & 31;
    int p = blockIdx.x * 8 + w;
    if (p >= PP) return;
    int y0 = y[2*p], y1 = y[2*p+1];
    const float* zl = Z + (size_t)y0 * HH;
    const float* zr = Z + (size_t)(MR + y1) * HH;
    int c = lane * 8;
    float s = 0.f;
    #pragma unroll
    for (int q = 0; q < 2; q++) {
        int cc = c + q * 4;
        float4 a = *(const float4*)(zl + cc);
        float4 b = *(const float4*)(zr + cc);
        float4 fb = *(const float4*)(fcb + cc);
        float4 fw = *(const float4*)(fc2W + cc);
        s += fmaxf(a.x + b.x + fb.x, 0.f) * fw.x;
        s += fmaxf(a.y + b.y + fb.y, 0.f) * fw.y;
        s += fmaxf(a.z + b.z + fb.z, 0.f) * fw.z;
        s += fmaxf(a.w + b.w + fb.w, 0.f) * fw.w;
    }
    #pragma unroll
    for (int o = 16; o > 0; o >>= 1) s += __shfl_xor_sync(~0u, s, o);
    if (lane == 0) out[p] = 1.f / (1.f + expf(-(s + fc2b[0])));
}

// ---------------- launch ----------------------------------------------------
extern "C" void kernel_launch(void* const* d_in, const int* in_sizes, int n_in,
                              void* d_out, int out_size) {
    const float* x_s  = (const float*)d_in[0];
    const float* x_t  = (const float*)d_in[1];
    const int*   ei_s = (const int*)  d_in[2];
    const int*   ei_t = (const int*)  d_in[3];
    const int*   y    = (const int*)  d_in[4];
    const float* W1   = (const float*)d_in[5];
    const float* b1   = (const float*)d_in[6];
    const float* W2   = (const float*)d_in[7];
    const float* b2   = (const float*)d_in[8];
    const float* fcW  = (const float*)d_in[9];
    const float* fcb  = (const float*)d_in[10];
    const float* fc2W = (const float*)d_in[11];
    const float* fc2b = (const float*)d_in[12];
    float* out = (float*)d_out;

    float *h, *dv;
    __nv_bfloat16 *Ah, *Al, *Ch, *Cl, *Bh, *Bl;
    int *deg, *rp, *wp, *cs, *bs, *bo;
    cudaGetSymbolAddress((void**)&h,  g_h);
    cudaGetSymbolAddress((void**)&Ah, g_Ah);
    cudaGetSymbolAddress((void**)&Al, g_Al);
    cudaGetSymbolAddress((void**)&Ch, g_Ch);
    cudaGetSymbolAddress((void**)&Cl, g_Cl);
    cudaGetSymbolAddress((void**)&Bh, g_Bh);
    cudaGetSymbolAddress((void**)&Bl, g_Bl);
    cudaGetSymbolAddress((void**)&dv, g_dinv);
    cudaGetSymbolAddress((void**)&deg, g_deg);
    cudaGetSymbolAddress((void**)&rp, g_rowptr);
    cudaGetSymbolAddress((void**)&wp, g_wptr);
    cudaGetSymbolAddress((void**)&cs, g_csr);
    cudaGetSymbolAddress((void**)&bs, g_bsum);
    cudaGetSymbolAddress((void**)&bo, g_boff);

    cudaFuncSetAttribute(k_gemm_bf<0>, cudaFuncAttributeMaxDynamicSharedMemorySize, 81920);
    cudaFuncSetAttribute(k_gemm_bf<1>, cudaFuncAttributeMaxDynamicSharedMemorySize, 81920);
    cudaFuncSetAttribute(k_gemm_bf<2>, cudaFuncAttributeMaxDynamicSharedMemorySize, 81920);

    // weights: W1t@0, W2t@32768, fcTop@98304, fcBot@163840
    k_wsplit<<<dim3(DIN/32, HH/32), dim3(32,8)>>>(W1, Bh, Bl, DIN, HH);
    k_wsplit<<<dim3(HH/32, HH/32), dim3(32,8)>>>(W2, Bh + 32768, Bl + 32768, HH, HH);
    k_wsplit<<<dim3(HH/32, HH/32), dim3(32,8)>>>(fcW, Bh + 98304, Bl + 98304, HH, HH);
    k_wsplit<<<dim3(HH/32, HH/32), dim3(32,8)>>>(fcW + (size_t)HH * HH, Bh + 163840, Bl + 163840, HH, HH);

    dim3 gn((NN + 255) / 256, 2), ge((EE + 255) / 256, 2);
    k_init_deg<<<gn, 256>>>(deg);
    k_count<<<ge, 256>>>(ei_s, ei_t, deg);
    k_scan1<<<dim3(NSB, 2), 256>>>(deg, bs, dv);
    k_scan2<<<dim3(1, 2), NSB>>>(bs, bo, rp);
    k_scan3<<<dim3(NSB, 2), 256>>>(deg, bo, rp, wp);
    k_fill<<<ge, 256>>>(ei_s, ei_t, wp, cs);

    dim3 gg(MT / 128, 2);
    k_aggx<<<MT / 8, dim3(32, 8)>>>(x_s, x_t, rp, cs, dv, Ah, Al);
    k_gemm_bf<0><<<gg, 256, 81920>>>(Ah, Al, Bh, Bl, Bh, Bl, b1, h, Ah, Al, DIN);
    k_aggh<<<MT / 4, dim3(64, 4)>>>(h, rp, cs, dv, Ch, Cl);
    k_gemm_bf<1><<<gg, 256, 81920>>>(Ch, Cl, Bh + 32768, Bl + 32768, Bh, Bl, b2, h, Ah, Al, HH);
    k_gemm_bf<2><<<gg, 256, 81920>>>(Ah, Al, Bh + 98304, Bl + 98304, Bh + 163840, Bl + 163840,
                                     b2, h, Ah, Al, HH);
    k_pair<<<(PP + 7) / 8, 256>>>(h, y, fcb, fc2W, fc2b, out);
}

// round 11
// speedup vs baseline: 1.1037x; 1.0142x over previous
#include <cuda_runtime.h>
#include <cuda_bf16.h>
#include <math.h>

#define NN 50000
#define EE 500000
#define DIN 128
#define HH 256
#define PP 100000
#define MR 50048
#define MT (2*MR)
#define NSB 128
#define CHUNK ((NN + NSB - 1) / NSB)
#define BST 40

__device__ float g_h [(size_t)MT*HH];
__device__ __nv_bfloat16 g_Ah[(size_t)MT*HH];
__device__ __nv_bfloat16 g_Al[(size_t)MT*HH];
__device__ __nv_bfloat16 g_Ch[(size_t)MT*HH];
__device__ __nv_bfloat16 g_Cl[(size_t)MT*HH];
__device__ __nv_bfloat16 g_Bh[229376];
__device__ __nv_bfloat16 g_Bl[229376];
__device__ int   g_deg[2*NN];
__device__ float g_dinv[2*NN];
__device__ int   g_rowptr[2*(NN+1)];
__device__ int   g_wptr[2*NN];
__device__ int   g_csr[2*EE];
__device__ int   g_bsum[2*NSB];
__device__ int   g_boff[2*NSB];

__device__ __forceinline__ void bsplit(float x, __nv_bfloat16& h, __nv_bfloat16& l) {
    h = __float2bfloat16_rn(x);
    l = __float2bfloat16_rn(x - __bfloat162float(h));
}

#define LDM4(R, A) asm volatile( \
    "ldmatrix.sync.aligned.m8n8.x4.shared.b16 {%0,%1,%2,%3}, [%4];" \
    : "=r"(R[0]),"=r"(R[1]),"=r"(R[2]),"=r"(R[3]) : "r"(A))
#define MMAB(D, A, B0, B1) asm volatile( \
    "mma.sync.aligned.m16n8k16.row.col.f32.bf16.bf16.f32 " \
    "{%0,%1,%2,%3},{%4,%5,%6,%7},{%8,%9},{%0,%1,%2,%3};" \
    : "+f"(D[0]),"+f"(D[1]),"+f"(D[2]),"+f"(D[3]) \
    : "r"(A[0]),"r"(A[1]),"r"(A[2]),"r"(A[3]),"r"(B0),"r"(B1))
#define CPA(D, S) asm volatile( \
    "cp.async.cg.shared.global [%0],[%1],16;" :: "r"(D),"l"(S))

// ---------------- prep: init deg + all 4 weight transpose/splits ------------
__global__ void k_prep(const float* __restrict__ W1, const float* __restrict__ W2,
                       const float* __restrict__ fcW,
                       __nv_bfloat16* __restrict__ Bh, __nv_bfloat16* __restrict__ Bl,
                       int* __restrict__ deg) {
    int b = blockIdx.x;
    if (b < 391) {                       // deg init: 2*NN ints
        int i = b * 256 + threadIdx.x;
        if (i < 2 * NN) deg[i] = 1;
        return;
    }
    b -= 391;
    const float* W; int K; __nv_bfloat16 *th, *tl;
    if (b < 32)       { W = W1;  K = DIN; th = Bh;          tl = Bl; }
    else if (b < 96)  { b -= 32;  W = W2;  K = HH; th = Bh + 32768;  tl = Bl + 32768; }
    else if (b < 160) { b -= 96;  W = fcW; K = HH; th = Bh + 98304;  tl = Bl + 98304; }
    else              { b -= 160; W = fcW + HH * HH; K = HH; th = Bh + 163840; tl = Bl + 163840; }
    int kblocks = K / 32;
    int k0 = (b % kblocks) * 32, n0 = (b / kblocks) * 32;
    __shared__ float sh[32][33];
    int tx = threadIdx.x & 31, ty = threadIdx.x >> 5;
    #pragma unroll
    for (int j = 0; j < 4; j++)
        sh[ty + j * 8][tx] = W[(size_t)(k0 + ty + j * 8) * HH + n0 + tx];
    __syncthreads();
    #pragma unroll
    for (int j = 0; j < 4; j++) {
        int nn = ty + j * 8;
        float v = sh[tx][nn];
        __nv_bfloat16 h, l;
        bsplit(v, h, l);
        th[(size_t)(n0 + nn) * K + k0 + tx] = h;
        tl[(size_t)(n0 + nn) * K + k0 + tx] = l;
    }
}

// ---------------- CSR build (gridDim.y = side) ------------------------------
__global__ void k_count(const int* __restrict__ es, const int* __restrict__ et,
                        int* __restrict__ deg) {
    int e = blockIdx.x * blockDim.x + threadIdx.x;
    const int* ei = blockIdx.y ? et : es;
    if (e < EE) atomicAdd(&deg[blockIdx.y * NN + ei[EE + e]], 1);
}
__global__ void k_scan1(const int* __restrict__ deg, int* __restrict__ bsum,
                        float* __restrict__ dinv) {
    const int* d = deg + blockIdx.y * NN;
    float* dv = dinv + blockIdx.y * NN;
    int lo = blockIdx.x * CHUNK, hi = min(lo + CHUNK, NN);
    int s = 0;
    for (int i = lo + threadIdx.x; i < hi; i += 256) {
        int dg = d[i];
        dv[i] = rsqrtf((float)dg);
        s += dg - 1;
    }
    __shared__ int sh[8];
    int lane = threadIdx.x & 31, w = threadIdx.x >> 5;
    #pragma unroll
    for (int o = 16; o > 0; o >>= 1) s += __shfl_down_sync(~0u, s, o);
    if (lane == 0) sh[w] = s;
    __syncthreads();
    if (threadIdx.x == 0) {
        int t = 0;
        #pragma unroll
        for (int j = 0; j < 8; j++) t += sh[j];
        bsum[blockIdx.y * NSB + blockIdx.x] = t;
    }
}
__global__ void k_scan2(const int* __restrict__ bsum, int* __restrict__ boff,
                        int* __restrict__ rowptr) {
    __shared__ int sb[NSB];
    int t = threadIdx.x, side = blockIdx.y;
    int orig = bsum[side * NSB + t];
    sb[t] = orig;
    __syncthreads();
    for (int o = 1; o < NSB; o <<= 1) {
        int v = (t >= o) ? sb[t - o] : 0;
        __syncthreads();
        sb[t] += v;
        __syncthreads();
    }
    boff[side * NSB + t] = sb[t] - orig;
    if (t == 0) rowptr[side * (NN + 1) + NN] = EE;
}
__global__ void k_scan3(const int* __restrict__ deg, const int* __restrict__ boff,
                        int* __restrict__ rowptr, int* __restrict__ wptr) {
    int side = blockIdx.y;
    const int* d = deg + side * NN;
    int* rp = rowptr + side * (NN + 1);
    int* wp = wptr + side * NN;
    int lo = blockIdx.x * CHUNK, hi = min(lo + CHUNK, NN);
    __shared__ int wsum[8];
    __shared__ int srun;
    if (threadIdx.x == 0) srun = boff[side * NSB + blockIdx.x];
    __syncthreads();
    int lane = threadIdx.x & 31, w = threadIdx.x >> 5;
    for (int t0 = lo; t0 < hi; t0 += 256) {
        int i = t0 + threadIdx.x;
        int v = (i < hi) ? d[i] - 1 : 0;
        int incl = v;
        #pragma unroll
        for (int o = 1; o < 32; o <<= 1) {
            int u = __shfl_up_sync(~0u, incl, o);
            if (lane >= o) incl += u;
        }
        if (lane == 31) wsum[w] = incl;
        __syncthreads();
        int woff = 0;
        for (int j = 0; j < w; j++) woff += wsum[j];
        if (i < hi) { int e = srun + woff + incl - v; rp[i] = e; wp[i] = e; }
        __syncthreads();
        if (threadIdx.x == 255) srun += woff + incl;
        __syncthreads();
    }
}
__global__ void k_fill(const int* __restrict__ es, const int* __restrict__ et,
                       int* __restrict__ wptr, int* __restrict__ csr) {
    int e = blockIdx.x * blockDim.x + threadIdx.x;
    const int* ei = blockIdx.y ? et : es;
    if (e < EE) {
        int p = atomicAdd(&wptr[blockIdx.y * NN + ei[EE + e]], 1);
        csr[blockIdx.y * EE + p] = ei[e];
    }
}

// ---------------- agg0: splits of norm-agg of raw x (128 cols) --------------
__global__ __launch_bounds__(256, 4)
void k_aggx(const float* __restrict__ xs, const float* __restrict__ xt,
            const int* __restrict__ rowptr, const int* __restrict__ csr,
            const float* __restrict__ dinv,
            __nv_bfloat16* __restrict__ oh, __nv_bfloat16* __restrict__ ol) {
    int r = blockIdx.x * 8 + threadIdx.y;
    if (r >= MT) return;
    int side = r >= MR;
    int node = r - side * MR;
    int c = threadIdx.x * 4;
    union { __nv_bfloat16 b[4]; uint2 u; } H, L;
    if (node >= NN) {
        H.u = make_uint2(0, 0);
        *(uint2*)(oh + (size_t)r * DIN + c) = H.u;
        *(uint2*)(ol + (size_t)r * DIN + c) = H.u;
        return;
    }
    const float* x = side ? xt : xs;
    const float* dv = dinv + side * NN;
    const int* rp = rowptr + side * (NN + 1);
    const int* cs = csr + side * EE;
    float di = dv[node];
    float4 v = *(const float4*)(x + (size_t)node * DIN + c);
    float w0 = di * di;
    float4 acc = make_float4(v.x*w0, v.y*w0, v.z*w0, v.w*w0);
    int lo = rp[node], hi = rp[node + 1];
    for (int e = lo; e < hi; e++) {
        int s = cs[e];
        float w = di * dv[s];
        float4 u = *(const float4*)(x + (size_t)s * DIN + c);
        acc.x += w*u.x; acc.y += w*u.y; acc.z += w*u.z; acc.w += w*u.w;
    }
    bsplit(acc.x, H.b[0], L.b[0]); bsplit(acc.y, H.b[1], L.b[1]);
    bsplit(acc.z, H.b[2], L.b[2]); bsplit(acc.w, H.b[3], L.b[3]);
    *(uint2*)(oh + (size_t)r * DIN + c) = H.u;
    *(uint2*)(ol + (size_t)r * DIN + c) = L.u;
}

// ---------------- agg1: splits of norm-agg of h (256 cols) ------------------
__global__ __launch_bounds__(256, 4)
void k_aggh(const float* __restrict__ h, const int* __restrict__ rowptr,
            const int* __restrict__ csr, const float* __restrict__ dinv,
            __nv_bfloat16* __restrict__ oh, __nv_bfloat16* __restrict__ ol) {
    int r = blockIdx.x * 4 + threadIdx.y;
    if (r >= MT) return;
    int side = r >= MR;
    int node = r - side * MR;
    int c = threadIdx.x * 4;
    union { __nv_bfloat16 b[4]; uint2 u; } H, L;
    if (node >= NN) {
        H.u = make_uint2(0, 0);
        *(uint2*)(oh + (size_t)r * HH + c) = H.u;
        *(uint2*)(ol + (size_t)r * HH + c) = H.u;
        return;
    }
    const float* dv = dinv + side * NN;
    const int* rp = rowptr + side * (NN + 1);
    const int* cs = csr + side * EE;
    const float* hb = h + (size_t)side * MR * HH;
    float di = dv[node];
    float4 v = *(const float4*)(h + (size_t)r * HH + c);
    float w0 = di * di;
    float4 acc = make_float4(v.x*w0, v.y*w0, v.z*w0, v.w*w0);
    int lo = rp[node], hi = rp[node + 1];
    for (int e = lo; e < hi; e++) {
        int s = cs[e];
        float w = di * dv[s];
        float4 u = *(const float4*)(hb + (size_t)s * HH + c);
        acc.x += w*u.x; acc.y += w*u.y; acc.z += w*u.z; acc.w += w*u.w;
    }
    bsplit(acc.x, H.b[0], L.b[0]); bsplit(acc.y, H.b[1], L.b[1]);
    bsplit(acc.z, H.b[2], L.b[2]); bsplit(acc.w, H.b[3], L.b[3]);
    *(uint2*)(oh + (size_t)r * HH + c) = H.u;
    *(uint2*)(ol + (size_t)r * HH + c) = L.u;
}

// ---------------- bf16x3 GEMM, reg-lean pass ordering, 2 CTAs/SM ------------
template<int MODE>
__global__ __launch_bounds__(256, 2)
void k_gemm_bf(const __nv_bfloat16* __restrict__ Ah, const __nv_bfloat16* __restrict__ Al,
               const __nv_bfloat16* __restrict__ Bth, const __nv_bfloat16* __restrict__ Btl,
               const __nv_bfloat16* __restrict__ B2h, const __nv_bfloat16* __restrict__ B2l,
               const float* __restrict__ bias, float* __restrict__ Cf,
               __nv_bfloat16* __restrict__ Oh, __nv_bfloat16* __restrict__ Ol, int K) {
    extern __shared__ __nv_bfloat16 smem_dyn[];
    unsigned smb = (unsigned)__cvta_generic_to_shared(smem_dyn);
    int tid = threadIdx.x, lane = tid & 31, wid = tid >> 5;
    int wm = wid & 1, wn = wid >> 1;
    int rb = blockIdx.x * 128, cb = blockIdx.y * 128;
    int T = K >> 5;
    const __nv_bfloat16* bh_src = (MODE == 2 && rb >= MR) ? B2h : Bth;
    const __nv_bfloat16* bl_src = (MODE == 2 && rb >= MR) ? B2l : Btl;

    float acc[4][4][4];
    #pragma unroll
    for (int a = 0; a < 4; a++)
        #pragma unroll
        for (int b = 0; b < 4; b++)
            #pragma unroll
            for (int c = 0; c < 4; c++) acc[a][b][c] = 0.f;

    int srow = tid >> 1, half = tid & 1;
    const __nv_bfloat16* pa = Ah + (size_t)(rb + srow) * K + half * 16;
    const __nv_bfloat16* pl = Al + (size_t)(rb + srow) * K + half * 16;
    const __nv_bfloat16* pb = bh_src + (size_t)(cb + srow) * K + half * 16;
    const __nv_bfloat16* pq = bl_src + (size_t)(cb + srow) * K + half * 16;
    unsigned sd = (unsigned)((srow * BST + half * 16) * 2);

    auto stage = [&](int t, int buf) {
        unsigned o = smb + buf * 10240 + sd;
        CPA(o,         pa + t * 32); CPA(o + 16,    pa + t * 32 + 8);
        CPA(o + 20480, pl + t * 32); CPA(o + 20496, pl + t * 32 + 8);
        CPA(o + 40960, pb + t * 32); CPA(o + 40976, pb + t * 32 + 8);
        CPA(o + 61440, pq + t * 32); CPA(o + 61456, pq + t * 32 + 8);
    };

    stage(0, 0);
    asm volatile("cp.async.commit_group;");

    for (int t = 0; t < T; t++) {
        int buf = t & 1;
        if (t + 1 < T) {
            stage(t + 1, buf ^ 1);
            asm volatile("cp.async.commit_group;");
            asm volatile("cp.async.wait_group 1;");
        } else {
            asm volatile("cp.async.wait_group 0;");
        }
        __syncthreads();

        unsigned pAh = smb + buf * 10240;
        unsigned pAl = pAh + 20480;
        unsigned pBh = pAh + 40960;
        unsigned pBl = pAh + 61440;

        #pragma unroll
        for (int ks = 0; ks < 2; ks++) {
            unsigned ah[4][4], bf[2][4], at[4];
            int ach = ks * 2 + (lane >> 4);
            int arow = wm * 64 + (lane & 15);
            #pragma unroll
            for (int mt = 0; mt < 4; mt++)
                LDM4(ah[mt], pAh + (unsigned)(((arow + mt * 16) * BST + ach * 8) * 2));
            int bch = ks * 2 + ((lane >> 3) & 1);
            int brow = wn * 32 + (lane & 7) + (lane >> 4) * 8;
            unsigned offb0 = (unsigned)((brow * BST + bch * 8) * 2);
            unsigned offb1 = (unsigned)(((brow + 16) * BST + bch * 8) * 2);
            LDM4(bf[0], pBh + offb0);
            LDM4(bf[1], pBh + offb1);
            #pragma unroll
            for (int mt = 0; mt < 4; mt++)
                #pragma unroll
                for (int nt = 0; nt < 4; nt++)
                    MMAB(acc[mt][nt], ah[mt], bf[nt >> 1][(nt & 1) * 2], bf[nt >> 1][(nt & 1) * 2 + 1]);
            #pragma unroll
            for (int mt = 0; mt < 4; mt++) {
                LDM4(at, pAl + (unsigned)(((arow + mt * 16) * BST + ach * 8) * 2));
                #pragma unroll
                for (int nt = 0; nt < 4; nt++)
                    MMAB(acc[mt][nt], at, bf[nt >> 1][(nt & 1) * 2], bf[nt >> 1][(nt & 1) * 2 + 1]);
            }
            LDM4(bf[0], pBl + offb0);
            LDM4(bf[1], pBl + offb1);
            #pragma unroll
            for (int mt = 0; mt < 4; mt++)
                #pragma unroll
                for (int nt = 0; nt < 4; nt++)
                    MMAB(acc[mt][nt], ah[mt], bf[nt >> 1][(nt & 1) * 2], bf[nt >> 1][(nt & 1) * 2 + 1]);
        }
        __syncthreads();
    }

    int g = lane >> 2, tg = lane & 3;
    #pragma unroll
    for (int mt = 0; mt < 4; mt++) {
        int r0 = rb + wm * 64 + mt * 16 + g;
        #pragma unroll
        for (int nt = 0; nt < 4; nt++) {
            int c = cb + wn * 32 + nt * 8 + tg * 2;
            float2 bv = make_float2(0.f, 0.f);
            if (MODE < 2) bv = *(const float2*)(bias + c);
            #pragma unroll
            for (int hrow = 0; hrow < 2; hrow++) {
                int r = r0 + hrow * 8;
                float v0 = acc[mt][nt][hrow * 2];
                float v1 = acc[mt][nt][hrow * 2 + 1];
                if (MODE < 2) {
                    v0 = fmaxf(v0 + bv.x, 0.f);
                    v1 = fmaxf(v1 + bv.y, 0.f);
                }
                if (MODE == 1) {
                    __nv_bfloat16 h0, l0, h1, l1;
                    bsplit(v0, h0, l0); bsplit(v1, h1, l1);
                    *(__nv_bfloat162*)(Oh + (size_t)r * HH + c) = __nv_bfloat162(h0, h1);
                    *(__nv_bfloat162*)(Ol + (size_t)r * HH + c) = __nv_bfloat162(l0, l1);
                } else {
                    *(float2*)(Cf + (size_t)r * HH + c) = make_float2(v0, v1);
                }
            }
        }
    }
}

// ---------------- pair epilogue ---------------------------------------------
__global__ __launch_bounds__(256)
void k_pair(const float* __restrict__ Z, const int* __restrict__ y,
            const float* __restrict__ fcb, const float* __restrict__ fc2W,
            const float* __restrict__ fc2b, float* __restrict__ out) {
    int w = threadIdx.x >> 5, lane = threadIdx.x & 31;
    int p = blockIdx.x * 8 + w;
    if (p >= PP) return;
    int y0 = y[2*p], y1 = y[2*p+1];
    const float* zl = Z + (size_t)y0 * HH;
    const float* zr = Z + (size_t)(MR + y1) * HH;
    int c = lane * 8;
    float s = 0.f;
    #pragma unroll
    for (int q = 0; q < 2; q++) {
        int cc = c + q * 4;
        float4 a = *(const float4*)(zl + cc);
        float4 b = *(const float4*)(zr + cc);
        float4 fb = *(const float4*)(fcb + cc);
        float4 fw = *(const float4*)(fc2W + cc);
        s += fmaxf(a.x + b.x + fb.x, 0.f) * fw.x;
        s += fmaxf(a.y + b.y + fb.y, 0.f) * fw.y;
        s += fmaxf(a.z + b.z + fb.z, 0.f) * fw.z;
        s += fmaxf(a.w + b.w + fb.w, 0.f) * fw.w;
    }
    #pragma unroll
    for (int o = 16; o > 0; o >>= 1) s += __shfl_xor_sync(~0u, s, o);
    if (lane == 0) out[p] = 1.f / (1.f + expf(-(s + fc2b[0])));
}

// ---------------- launch ----------------------------------------------------
extern "C" void kernel_launch(void* const* d_in, const int* in_sizes, int n_in,
                              void* d_out, int out_size) {
    const float* x_s  = (const float*)d_in[0];
    const float* x_t  = (const float*)d_in[1];
    const int*   ei_s = (const int*)  d_in[2];
    const int*   ei_t = (const int*)  d_in[3];
    const int*   y    = (const int*)  d_in[4];
    const float* W1   = (const float*)d_in[5];
    const float* b1   = (const float*)d_in[6];
    const float* W2   = (const float*)d_in[7];
    const float* b2   = (const float*)d_in[8];
    const float* fcW  = (const float*)d_in[9];
    const float* fcb  = (const float*)d_in[10];
    const float* fc2W = (const float*)d_in[11];
    const float* fc2b = (const float*)d_in[12];
    float* out = (float*)d_out;

    float *h, *dv;
    __nv_bfloat16 *Ah, *Al, *Ch, *Cl, *Bh, *Bl;
    int *deg, *rp, *wp, *cs, *bs, *bo;
    cudaGetSymbolAddress((void**)&h,  g_h);
    cudaGetSymbolAddress((void**)&Ah, g_Ah);
    cudaGetSymbolAddress((void**)&Al, g_Al);
    cudaGetSymbolAddress((void**)&Ch, g_Ch);
    cudaGetSymbolAddress((void**)&Cl, g_Cl);
    cudaGetSymbolAddress((void**)&Bh, g_Bh);
    cudaGetSymbolAddress((void**)&Bl, g_Bl);
    cudaGetSymbolAddress((void**)&dv, g_dinv);
    cudaGetSymbolAddress((void**)&deg, g_deg);
    cudaGetSymbolAddress((void**)&rp, g_rowptr);
    cudaGetSymbolAddress((void**)&wp, g_wptr);
    cudaGetSymbolAddress((void**)&cs, g_csr);
    cudaGetSymbolAddress((void**)&bs, g_bsum);
    cudaGetSymbolAddress((void**)&bo, g_boff);

    cudaFuncSetAttribute(k_gemm_bf<0>, cudaFuncAttributeMaxDynamicSharedMemorySize, 81920);
    cudaFuncSetAttribute(k_gemm_bf<1>, cudaFuncAttributeMaxDynamicSharedMemorySize, 81920);
    cudaFuncSetAttribute(k_gemm_bf<2>, cudaFuncAttributeMaxDynamicSharedMemorySize, 81920);

    // prep: deg init (391 blocks) + W1 (32) + W2 (64) + fcTop (64) + fcBot (64)
    k_prep<<<615, 256>>>(W1, W2, fcW, Bh, Bl, deg);

    dim3 ge((EE + 255) / 256, 2);
    k_count<<<ge, 256>>>(ei_s, ei_t, deg);
    k_scan1<<<dim3(NSB, 2), 256>>>(deg, bs, dv);
    k_scan2<<<dim3(1, 2), NSB>>>(bs, bo, rp);
    k_scan3<<<dim3(NSB, 2), 256>>>(deg, bo, rp, wp);
    k_fill<<<ge, 256>>>(ei_s, ei_t, wp, cs);

    dim3 gg(MT / 128, 2);
    k_aggx<<<MT / 8, dim3(32, 8)>>>(x_s, x_t, rp, cs, dv, Ah, Al);
    k_gemm_bf<0><<<gg, 256, 81920>>>(Ah, Al, Bh, Bl, Bh, Bl, b1, h, Ah, Al, DIN);
    k_aggh<<<MT / 4, dim3(64, 4)>>>(h, rp, cs, dv, Ch, Cl);
    k_gemm_bf<1><<<gg, 256, 81920>>>(Ch, Cl, Bh + 32768, Bl + 32768, Bh, Bl, b2, h, Ah, Al, HH);
    k_gemm_bf<2><<<gg, 256, 81920>>>(Ah, Al, Bh + 98304, Bl + 98304, Bh + 163840, Bl + 163840,
                                     b2, h, Ah, Al, HH);
    k_pair<<<(PP + 7) / 8, 256>>>(h, y, fcb, fc2W, fc2b, out);
}

// round 12
// speedup vs baseline: 1.1511x; 1.0430x over previous
#include <cuda_runtime.h>
#include <cuda_bf16.h>
#include <math.h>

#define NN 50000
#define EE 500000
#define DIN 128
#define HH 256
#define PP 100000
#define MR 50048
#define MT (2*MR)
#define NSB 128
#define CHUNK ((NN + NSB - 1) / NSB)
#define BST 40

__device__ float g_h [(size_t)MT*HH];
__device__ __nv_bfloat16 g_Ah[(size_t)MT*HH];
__device__ __nv_bfloat16 g_Al[(size_t)MT*HH];
__device__ __nv_bfloat16 g_Ch[(size_t)MT*HH];
__device__ __nv_bfloat16 g_Cl[(size_t)MT*HH];
__device__ __nv_bfloat16 g_Bh[229376];
__device__ __nv_bfloat16 g_Bl[229376];
__device__ int   g_deg[2*NN];
__device__ float g_dinv[2*NN];
__device__ int   g_rowptr[2*(NN+1)];
__device__ int   g_wptr[2*NN];
__device__ int   g_csr[2*EE];
__device__ int   g_bsum[2*NSB];

__device__ __forceinline__ void bsplit(float x, __nv_bfloat16& h, __nv_bfloat16& l) {
    h = __float2bfloat16_rn(x);
    l = __float2bfloat16_rn(x - __bfloat162float(h));
}

#define LDM4(R, A) asm volatile( \
    "ldmatrix.sync.aligned.m8n8.x4.shared.b16 {%0,%1,%2,%3}, [%4];" \
    : "=r"(R[0]),"=r"(R[1]),"=r"(R[2]),"=r"(R[3]) : "r"(A))
#define MMAB(D, A, B0, B1) asm volatile( \
    "mma.sync.aligned.m16n8k16.row.col.f32.bf16.bf16.f32 " \
    "{%0,%1,%2,%3},{%4,%5,%6,%7},{%8,%9},{%0,%1,%2,%3};" \
    : "+f"(D[0]),"+f"(D[1]),"+f"(D[2]),"+f"(D[3]) \
    : "r"(A[0]),"r"(A[1]),"r"(A[2]),"r"(A[3]),"r"(B0),"r"(B1))
#define CPA(D, S) asm volatile( \
    "cp.async.cg.shared.global [%0],[%1],16;" :: "r"(D),"l"(S))

// ---------------- prep: init deg + all 4 weight transpose/splits ------------
__global__ void k_prep(const float* __restrict__ W1, const float* __restrict__ W2,
                       const float* __restrict__ fcW,
                       __nv_bfloat16* __restrict__ Bh, __nv_bfloat16* __restrict__ Bl,
                       int* __restrict__ deg) {
    int b = blockIdx.x;
    if (b < 391) {
        int i = b * 256 + threadIdx.x;
        if (i < 2 * NN) deg[i] = 1;
        return;
    }
    b -= 391;
    const float* W; int K; __nv_bfloat16 *th, *tl;
    if (b < 32)       { W = W1;  K = DIN; th = Bh;          tl = Bl; }
    else if (b < 96)  { b -= 32;  W = W2;  K = HH; th = Bh + 32768;  tl = Bl + 32768; }
    else if (b < 160) { b -= 96;  W = fcW; K = HH; th = Bh + 98304;  tl = Bl + 98304; }
    else              { b -= 160; W = fcW + HH * HH; K = HH; th = Bh + 163840; tl = Bl + 163840; }
    int kblocks = K / 32;
    int k0 = (b % kblocks) * 32, n0 = (b / kblocks) * 32;
    __shared__ float sh[32][33];
    int tx = threadIdx.x & 31, ty = threadIdx.x >> 5;
    #pragma unroll
    for (int j = 0; j < 4; j++)
        sh[ty + j * 8][tx] = W[(size_t)(k0 + ty + j * 8) * HH + n0 + tx];
    __syncthreads();
    #pragma unroll
    for (int j = 0; j < 4; j++) {
        int nn = ty + j * 8;
        float v = sh[tx][nn];
        __nv_bfloat16 h, l;
        bsplit(v, h, l);
        th[(size_t)(n0 + nn) * K + k0 + tx] = h;
        tl[(size_t)(n0 + nn) * K + k0 + tx] = l;
    }
}

// ---------------- CSR build (gridDim.y = side) ------------------------------
__global__ void k_count(const int* __restrict__ es, const int* __restrict__ et,
                        int* __restrict__ deg) {
    int e = blockIdx.x * blockDim.x + threadIdx.x;
    const int* ei = blockIdx.y ? et : es;
    if (e < EE) atomicAdd(&deg[blockIdx.y * NN + ei[EE + e]], 1);
}
__global__ void k_scan1(const int* __restrict__ deg, int* __restrict__ bsum,
                        float* __restrict__ dinv) {
    const int* d = deg + blockIdx.y * NN;
    float* dv = dinv + blockIdx.y * NN;
    int lo = blockIdx.x * CHUNK, hi = min(lo + CHUNK, NN);
    int s = 0;
    for (int i = lo + threadIdx.x; i < hi; i += 256) {
        int dg = d[i];
        dv[i] = rsqrtf((float)dg);
        s += dg - 1;
    }
    __shared__ int sh[8];
    int lane = threadIdx.x & 31, w = threadIdx.x >> 5;
    #pragma unroll
    for (int o = 16; o > 0; o >>= 1) s += __shfl_down_sync(~0u, s, o);
    if (lane == 0) sh[w] = s;
    __syncthreads();
    if (threadIdx.x == 0) {
        int t = 0;
        #pragma unroll
        for (int j = 0; j < 8; j++) t += sh[j];
        bsum[blockIdx.y * NSB + blockIdx.x] = t;
    }
}
// scan3: per-block prefix over bsum computed in-kernel (scan2 folded in)
__global__ void k_scan3(const int* __restrict__ deg, const int* __restrict__ bsum,
                        int* __restrict__ rowptr, int* __restrict__ wptr) {
    int side = blockIdx.y;
    const int* d = deg + side * NN;
    int* rp = rowptr + side * (NN + 1);
    int* wp = wptr + side * NN;
    int lo = blockIdx.x * CHUNK, hi = min(lo + CHUNK, NN);
    __shared__ int wsum[8];
    __shared__ int srun;
    {
        int s = 0;
        for (int i = threadIdx.x; i < blockIdx.x; i += 256) s += bsum[side * NSB + i];
        int lane = threadIdx.x & 31, w = threadIdx.x >> 5;
        #pragma unroll
        for (int o = 16; o > 0; o >>= 1) s += __shfl_down_sync(~0u, s, o);
        if (lane == 0) wsum[w] = s;
        __syncthreads();
        if (threadIdx.x == 0) {
            int t = 0;
            #pragma unroll
            for (int j = 0; j < 8; j++) t += wsum[j];
            srun = t;
            if (blockIdx.x == 0) rp[NN] = EE;
        }
        __syncthreads();
    }
    int lane = threadIdx.x & 31, w = threadIdx.x >> 5;
    for (int t0 = lo; t0 < hi; t0 += 256) {
        int i = t0 + threadIdx.x;
        int v = (i < hi) ? d[i] - 1 : 0;
        int incl = v;
        #pragma unroll
        for (int o = 1; o < 32; o <<= 1) {
            int u = __shfl_up_sync(~0u, incl, o);
            if (lane >= o) incl += u;
        }
        if (lane == 31) wsum[w] = incl;
        __syncthreads();
        int woff = 0;
        for (int j = 0; j < w; j++) woff += wsum[j];
        if (i < hi) { int e = srun + woff + incl - v; rp[i] = e; wp[i] = e; }
        __syncthreads();
        if (threadIdx.x == 255) srun += woff + incl;
        __syncthreads();
    }
}
__global__ void k_fill(const int* __restrict__ es, const int* __restrict__ et,
                       int* __restrict__ wptr, int* __restrict__ csr) {
    int e = blockIdx.x * blockDim.x + threadIdx.x;
    const int* ei = blockIdx.y ? et : es;
    if (e < EE) {
        int p = atomicAdd(&wptr[blockIdx.y * NN + ei[EE + e]], 1);
        csr[blockIdx.y * EE + p] = ei[e];
    }
}

// ---------------- agg0: splits of norm-agg of raw x (128 cols) --------------
__global__ __launch_bounds__(256, 6)
void k_aggx(const float* __restrict__ xs, const float* __restrict__ xt,
            const int* __restrict__ rowptr, const int* __restrict__ csr,
            const float* __restrict__ dinv,
            __nv_bfloat16* __restrict__ oh, __nv_bfloat16* __restrict__ ol) {
    int r = blockIdx.x * 8 + threadIdx.y;
    if (r >= MT) return;
    int side = r >= MR;
    int node = r - side * MR;
    int c = threadIdx.x * 4;
    union { __nv_bfloat16 b[4]; uint2 u; } H, L;
    if (node >= NN) {
        H.u = make_uint2(0, 0);
        *(uint2*)(oh + (size_t)r * DIN + c) = H.u;
        *(uint2*)(ol + (size_t)r * DIN + c) = H.u;
        return;
    }
    const float* x = side ? xt : xs;
    const float* dv = dinv + side * NN;
    const int* rp = rowptr + side * (NN + 1);
    const int* cs = csr + side * EE;
    float di = dv[node];
    float4 v = *(const float4*)(x + (size_t)node * DIN + c);
    float w0 = di * di;
    float4 acc = make_float4(v.x*w0, v.y*w0, v.z*w0, v.w*w0);
    int lo = rp[node], hi = rp[node + 1];
    for (int e = lo; e < hi; e++) {
        int s = cs[e];
        float w = di * dv[s];
        float4 u = *(const float4*)(x + (size_t)s * DIN + c);
        acc.x += w*u.x; acc.y += w*u.y; acc.z += w*u.z; acc.w += w*u.w;
    }
    bsplit(acc.x, H.b[0], L.b[0]); bsplit(acc.y, H.b[1], L.b[1]);
    bsplit(acc.z, H.b[2], L.b[2]); bsplit(acc.w, H.b[3], L.b[3]);
    *(uint2*)(oh + (size_t)r * DIN + c) = H.u;
    *(uint2*)(ol + (size_t)r * DIN + c) = L.u;
}

// ---------------- agg1: splits of norm-agg of h (256 cols) ------------------
__global__ __launch_bounds__(256, 6)
void k_aggh(const float* __restrict__ h, const int* __restrict__ rowptr,
            const int* __restrict__ csr, const float* __restrict__ dinv,
            __nv_bfloat16* __restrict__ oh, __nv_bfloat16* __restrict__ ol) {
    int r = blockIdx.x * 4 + threadIdx.y;
    if (r >= MT) return;
    int side = r >= MR;
    int node = r - side * MR;
    int c = threadIdx.x * 4;
    union { __nv_bfloat16 b[4]; uint2 u; } H, L;
    if (node >= NN) {
        H.u = make_uint2(0, 0);
        *(uint2*)(oh + (size_t)r * HH + c) = H.u;
        *(uint2*)(ol + (size_t)r * HH + c) = H.u;
        return;
    }
    const float* dv = dinv + side * NN;
    const int* rp = rowptr + side * (NN + 1);
    const int* cs = csr + side * EE;
    const float* hb = h + (size_t)side * MR * HH;
    float di = dv[node];
    float4 v = *(const float4*)(h + (size_t)r * HH + c);
    float w0 = di * di;
    float4 acc = make_float4(v.x*w0, v.y*w0, v.z*w0, v.w*w0);
    int lo = rp[node], hi = rp[node + 1];
    for (int e = lo; e < hi; e++) {
        int s = cs[e];
        float w = di * dv[s];
        float4 u = *(const float4*)(hb + (size_t)s * HH + c);
        acc.x += w*u.x; acc.y += w*u.y; acc.z += w*u.z; acc.w += w*u.w;
    }
    bsplit(acc.x, H.b[0], L.b[0]); bsplit(acc.y, H.b[1], L.b[1]);
    bsplit(acc.z, H.b[2], L.b[2]); bsplit(acc.w, H.b[3], L.b[3]);
    *(uint2*)(oh + (size_t)r * HH + c) = H.u;
    *(uint2*)(ol + (size_t)r * HH + c) = L.u;
}

// ---------------- bf16x3 GEMM, reg-lean pass ordering, 2 CTAs/SM ------------
template<int MODE>
__global__ __launch_bounds__(256, 2)
void k_gemm_bf(const __nv_bfloat16* __restrict__ Ah, const __nv_bfloat16* __restrict__ Al,
               const __nv_bfloat16* __restrict__ Bth, const __nv_bfloat16* __restrict__ Btl,
               const __nv_bfloat16* __restrict__ B2h, const __nv_bfloat16* __restrict__ B2l,
               const float* __restrict__ bias, float* __restrict__ Cf,
               __nv_bfloat16* __restrict__ Oh, __nv_bfloat16* __restrict__ Ol, int K) {
    extern __shared__ __nv_bfloat16 smem_dyn[];
    unsigned smb = (unsigned)__cvta_generic_to_shared(smem_dyn);
    int tid = threadIdx.x, lane = tid & 31, wid = tid >> 5;
    int wm = wid & 1, wn = wid >> 1;
    int rb = blockIdx.x * 128, cb = blockIdx.y * 128;
    int T = K >> 5;
    const __nv_bfloat16* bh_src = (MODE == 2 && rb >= MR) ? B2h : Bth;
    const __nv_bfloat16* bl_src = (MODE == 2 && rb >= MR) ? B2l : Btl;

    float acc[4][4][4];
    #pragma unroll
    for (int a = 0; a < 4; a++)
        #pragma unroll
        for (int b = 0; b < 4; b++)
            #pragma unroll
            for (int c = 0; c < 4; c++) acc[a][b][c] = 0.f;

    int srow = tid >> 1, half = tid & 1;
    const __nv_bfloat16* pa = Ah + (size_t)(rb + srow) * K + half * 16;
    const __nv_bfloat16* pl = Al + (size_t)(rb + srow) * K + half * 16;
    const __nv_bfloat16* pb = bh_src + (size_t)(cb + srow) * K + half * 16;
    const __nv_bfloat16* pq = bl_src + (size_t)(cb + srow) * K + half * 16;
    unsigned sd = (unsigned)((srow * BST + half * 16) * 2);

    auto stage = [&](int t, int buf) {
        unsigned o = smb + buf * 10240 + sd;
        CPA(o,         pa + t * 32); CPA(o + 16,    pa + t * 32 + 8);
        CPA(o + 20480, pl + t * 32); CPA(o + 20496, pl + t * 32 + 8);
        CPA(o + 40960, pb + t * 32); CPA(o + 40976, pb + t * 32 + 8);
        CPA(o + 61440, pq + t * 32); CPA(o + 61456, pq + t * 32 + 8);
    };

    stage(0, 0);
    asm volatile("cp.async.commit_group;");

    for (int t = 0; t < T; t++) {
        int buf = t & 1;
        if (t + 1 < T) {
            stage(t + 1, buf ^ 1);
            asm volatile("cp.async.commit_group;");
            asm volatile("cp.async.wait_group 1;");
        } else {
            asm volatile("cp.async.wait_group 0;");
        }
        __syncthreads();

        unsigned pAh = smb + buf * 10240;
        unsigned pAl = pAh + 20480;
        unsigned pBh = pAh + 40960;
        unsigned pBl = pAh + 61440;

        #pragma unroll
        for (int ks = 0; ks < 2; ks++) {
            unsigned ah[4][4], bf[2][4], at[4];
            int ach = ks * 2 + (lane >> 4);
            int arow = wm * 64 + (lane & 15);
            #pragma unroll
            for (int mt = 0; mt < 4; mt++)
                LDM4(ah[mt], pAh + (unsigned)(((arow + mt * 16) * BST + ach * 8) * 2));
            int bch = ks * 2 + ((lane >> 3) & 1);
            int brow = wn * 32 + (lane & 7) + (lane >> 4) * 8;
            unsigned offb0 = (unsigned)((brow * BST + bch * 8) * 2);
            unsigned offb1 = (unsigned)(((brow + 16) * BST + bch * 8) * 2);
            LDM4(bf[0], pBh + offb0);
            LDM4(bf[1], pBh + offb1);
            #pragma unroll
            for (int mt = 0; mt < 4; mt++)
                #pragma unroll
                for (int nt = 0; nt < 4; nt++)
                    MMAB(acc[mt][nt], ah[mt], bf[nt >> 1][(nt & 1) * 2], bf[nt >> 1][(nt & 1) * 2 + 1]);
            #pragma unroll
            for (int mt = 0; mt < 4; mt++) {
                LDM4(at, pAl + (unsigned)(((arow + mt * 16) * BST + ach * 8) * 2));
                #pragma unroll
                for (int nt = 0; nt < 4; nt++)
                    MMAB(acc[mt][nt], at, bf[nt >> 1][(nt & 1) * 2], bf[nt >> 1][(nt & 1) * 2 + 1]);
            }
            LDM4(bf[0], pBl + offb0);
            LDM4(bf[1], pBl + offb1);
            #pragma unroll
            for (int mt = 0; mt < 4; mt++)
                #pragma unroll
                for (int nt = 0; nt < 4; nt++)
                    MMAB(acc[mt][nt], ah[mt], bf[nt >> 1][(nt & 1) * 2], bf[nt >> 1][(nt & 1) * 2 + 1]);
        }
        __syncthreads();
    }

    int g = lane >> 2, tg = lane & 3;
    #pragma unroll
    for (int mt = 0; mt < 4; mt++) {
        int r0 = rb + wm * 64 + mt * 16 + g;
        #pragma unroll
        for (int nt = 0; nt < 4; nt++) {
            int c = cb + wn * 32 + nt * 8 + tg * 2;
            float2 bv = make_float2(0.f, 0.f);
            if (MODE < 2) bv = *(const float2*)(bias + c);
            #pragma unroll
            for (int hrow = 0; hrow < 2; hrow++) {
                int r = r0 + hrow * 8;
                float v0 = acc[mt][nt][hrow * 2];
                float v1 = acc[mt][nt][hrow * 2 + 1];
                if (MODE < 2) {
                    v0 = fmaxf(v0 + bv.x, 0.f);
                    v1 = fmaxf(v1 + bv.y, 0.f);
                }
                if (MODE == 1) {
                    __nv_bfloat16 h0, l0, h1, l1;
                    bsplit(v0, h0, l0); bsplit(v1, h1, l1);
                    *(__nv_bfloat162*)(Oh + (size_t)r * HH + c) = __nv_bfloat162(h0, h1);
                    *(__nv_bfloat162*)(Ol + (size_t)r * HH + c) = __nv_bfloat162(l0, l1);
                } else {
                    *(float2*)(Cf + (size_t)r * HH + c) = make_float2(v0, v1);
                }
            }
        }
    }
}

// ---------------- pair epilogue ---------------------------------------------
__global__ __launch_bounds__(256)
void k_pair(const float* __restrict__ Z, const int* __restrict__ y,
            const float* __restrict__ fcb, const float* __restrict__ fc2W,
            const float* __restrict__ fc2b, float* __restrict__ out) {
    int w = threadIdx.x >> 5, lane = threadIdx.x & 31;
    int p = blockIdx.x * 8 + w;
    if (p >= PP) return;
    int y0 = y[2*p], y1 = y[2*p+1];
    const float* zl = Z + (size_t)y0 * HH;
    const float* zr = Z + (size_t)(MR + y1) * HH;
    int c = lane * 8;
    float s = 0.f;
    #pragma unroll
    for (int q = 0; q < 2; q++) {
        int cc = c + q * 4;
        float4 a = *(const float4*)(zl + cc);
        float4 b = *(const float4*)(zr + cc);
        float4 fb = *(const float4*)(fcb + cc);
        float4 fw = *(const float4*)(fc2W + cc);
        s += fmaxf(a.x + b.x + fb.x, 0.f) * fw.x;
        s += fmaxf(a.y + b.y + fb.y, 0.f) * fw.y;
        s += fmaxf(a.z + b.z + fb.z, 0.f) * fw.z;
        s += fmaxf(a.w + b.w + fb.w, 0.f) * fw.w;
    }
    #pragma unroll
    for (int o = 16; o > 0; o >>= 1) s += __shfl_xor_sync(~0u, s, o);
    if (lane == 0) out[p] = 1.f / (1.f + expf(-(s + fc2b[0])));
}

// ---------------- launch ----------------------------------------------------
extern "C" void kernel_launch(void* const* d_in, const int* in_sizes, int n_in,
                              void* d_out, int out_size) {
    const float* x_s  = (const float*)d_in[0];
    const float* x_t  = (const float*)d_in[1];
    const int*   ei_s = (const int*)  d_in[2];
    const int*   ei_t = (const int*)  d_in[3];
    const int*   y    = (const int*)  d_in[4];
    const float* W1   = (const float*)d_in[5];
    const float* b1   = (const float*)d_in[6];
    const float* W2   = (const float*)d_in[7];
    const float* b2   = (const float*)d_in[8];
    const float* fcW  = (const float*)d_in[9];
    const float* fcb  = (const float*)d_in[10];
    const float* fc2W = (const float*)d_in[11];
    const float* fc2b = (const float*)d_in[12];
    float* out = (float*)d_out;

    float *h, *dv;
    __nv_bfloat16 *Ah, *Al, *Ch, *Cl, *Bh, *Bl;
    int *deg, *rp, *wp, *cs, *bs;
    cudaGetSymbolAddress((void**)&h,  g_h);
    cudaGetSymbolAddress((void**)&Ah, g_Ah);
    cudaGetSymbolAddress((void**)&Al, g_Al);
    cudaGetSymbolAddress((void**)&Ch, g_Ch);
    cudaGetSymbolAddress((void**)&Cl, g_Cl);
    cudaGetSymbolAddress((void**)&Bh, g_Bh);
    cudaGetSymbolAddress((void**)&Bl, g_Bl);
    cudaGetSymbolAddress((void**)&dv, g_dinv);
    cudaGetSymbolAddress((void**)&deg, g_deg);
    cudaGetSymbolAddress((void**)&rp, g_rowptr);
    cudaGetSymbolAddress((void**)&wp, g_wptr);
    cudaGetSymbolAddress((void**)&cs, g_csr);
    cudaGetSymbolAddress((void**)&bs, g_bsum);

    cudaFuncSetAttribute(k_gemm_bf<0>, cudaFuncAttributeMaxDynamicSharedMemorySize, 81920);
    cudaFuncSetAttribute(k_gemm_bf<1>, cudaFuncAttributeMaxDynamicSharedMemorySize, 81920);
    cudaFuncSetAttribute(k_gemm_bf<2>, cudaFuncAttributeMaxDynamicSharedMemorySize, 81920);

    k_prep<<<615, 256>>>(W1, W2, fcW, Bh, Bl, deg);

    dim3 ge((EE + 255) / 256, 2);
    k_count<<<ge, 256>>>(ei_s, ei_t, deg);
    k_scan1<<<dim3(NSB, 2), 256>>>(deg, bs, dv);
    k_scan3<<<dim3(NSB, 2), 256>>>(deg, bs, rp, wp);
    k_fill<<<ge, 256>>>(ei_s, ei_t, wp, cs);

    dim3 gg(MT / 128, 2);
    k_aggx<<<MT / 8, dim3(32, 8)>>>(x_s, x_t, rp, cs, dv, Ah, Al);
    k_gemm_bf<0><<<gg, 256, 81920>>>(Ah, Al, Bh, Bl, Bh, Bl, b1, h, Ah, Al, DIN);
    k_aggh<<<MT / 4, dim3(64, 4)>>>(h, rp, cs, dv, Ch, Cl);
    k_gemm_bf<1><<<gg, 256, 81920>>>(Ch, Cl, Bh + 32768, Bl + 32768, Bh, Bl, b2, h, Ah, Al, HH);
    k_gemm_bf<2><<<gg, 256, 81920>>>(Ah, Al, Bh + 98304, Bl + 98304, Bh + 163840, Bl + 163840,
                                     b2, h, Ah, Al, HH);
    k_pair<<<(PP + 7) / 8, 256>>>(h, y, fcb, fc2W, fc2b, out);
}

// round 13
// speedup vs baseline: 1.1624x; 1.0098x over previous
#include <cuda_runtime.h>
#include <cuda_bf16.h>
#include <math.h>

#define NN 50000
#define EE 500000
#define DIN 128
#define HH 256
#define PP 100000
#define MR 50048
#define MT (2*MR)
#define NSB 128
#define CHUNK ((NN + NSB - 1) / NSB)
#define BST 40

__device__ float g_h [(size_t)MT*HH];
__device__ __nv_bfloat16 g_Ah[(size_t)MT*HH];
__device__ __nv_bfloat16 g_Al[(size_t)MT*HH];
__device__ __nv_bfloat16 g_Ch[(size_t)MT*HH];
__device__ __nv_bfloat16 g_Cl[(size_t)MT*HH];
__device__ __nv_bfloat16 g_Bh[229376];
__device__ __nv_bfloat16 g_Bl[229376];
__device__ int   g_deg[2*NN];
__device__ float g_dinv[2*NN];
__device__ int   g_rowptr[2*(NN+1)];
__device__ int   g_wptr[2*NN];
__device__ int   g_csr[2*EE];
__device__ int   g_bsum[2*NSB];

__device__ __forceinline__ void bsplit(float x, __nv_bfloat16& h, __nv_bfloat16& l) {
    h = __float2bfloat16_rn(x);
    l = __float2bfloat16_rn(x - __bfloat162float(h));
}

#define LDM4(R, A) asm volatile( \
    "ldmatrix.sync.aligned.m8n8.x4.shared.b16 {%0,%1,%2,%3}, [%4];" \
    : "=r"(R[0]),"=r"(R[1]),"=r"(R[2]),"=r"(R[3]) : "r"(A))
#define MMAB(D, A, B0, B1) asm volatile( \
    "mma.sync.aligned.m16n8k16.row.col.f32.bf16.bf16.f32 " \
    "{%0,%1,%2,%3},{%4,%5,%6,%7},{%8,%9},{%0,%1,%2,%3};" \
    : "+f"(D[0]),"+f"(D[1]),"+f"(D[2]),"+f"(D[3]) \
    : "r"(A[0]),"r"(A[1]),"r"(A[2]),"r"(A[3]),"r"(B0),"r"(B1))
#define CPA(D, S) asm volatile( \
    "cp.async.cg.shared.global [%0],[%1],16;" :: "r"(D),"l"(S))

// ---------------- prep: init deg + all 4 weight transpose/splits ------------
__global__ void k_prep(const float* __restrict__ W1, const float* __restrict__ W2,
                       const float* __restrict__ fcW,
                       __nv_bfloat16* __restrict__ Bh, __nv_bfloat16* __restrict__ Bl,
                       int* __restrict__ deg) {
    int b = blockIdx.x;
    if (b < 391) {
        int i = b * 256 + threadIdx.x;
        if (i < 2 * NN) deg[i] = 1;
        return;
    }
    b -= 391;
    const float* W; int K; __nv_bfloat16 *th, *tl;
    if (b < 32)       { W = W1;  K = DIN; th = Bh;          tl = Bl; }
    else if (b < 96)  { b -= 32;  W = W2;  K = HH; th = Bh + 32768;  tl = Bl + 32768; }
    else if (b < 160) { b -= 96;  W = fcW; K = HH; th = Bh + 98304;  tl = Bl + 98304; }
    else              { b -= 160; W = fcW + HH * HH; K = HH; th = Bh + 163840; tl = Bl + 163840; }
    int kblocks = K / 32;
    int k0 = (b % kblocks) * 32, n0 = (b / kblocks) * 32;
    __shared__ float sh[32][33];
    int tx = threadIdx.x & 31, ty = threadIdx.x >> 5;
    #pragma unroll
    for (int j = 0; j < 4; j++)
        sh[ty + j * 8][tx] = W[(size_t)(k0 + ty + j * 8) * HH + n0 + tx];
    __syncthreads();
    #pragma unroll
    for (int j = 0; j < 4; j++) {
        int nn = ty + j * 8;
        float v = sh[tx][nn];
        __nv_bfloat16 h, l;
        bsplit(v, h, l);
        th[(size_t)(n0 + nn) * K + k0 + tx] = h;
        tl[(size_t)(n0 + nn) * K + k0 + tx] = l;
    }
}

// ---------------- CSR build (gridDim.y = side) ------------------------------
__global__ void k_count(const int* __restrict__ es, const int* __restrict__ et,
                        int* __restrict__ deg) {
    int e = blockIdx.x * blockDim.x + threadIdx.x;
    const int* ei = blockIdx.y ? et : es;
    if (e < EE) atomicAdd(&deg[blockIdx.y * NN + ei[EE + e]], 1);
}
__global__ void k_scan1(const int* __restrict__ deg, int* __restrict__ bsum,
                        float* __restrict__ dinv) {
    const int* d = deg + blockIdx.y * NN;
    float* dv = dinv + blockIdx.y * NN;
    int lo = blockIdx.x * CHUNK, hi = min(lo + CHUNK, NN);
    int s = 0;
    for (int i = lo + threadIdx.x; i < hi; i += 256) {
        int dg = d[i];
        dv[i] = rsqrtf((float)dg);
        s += dg - 1;
    }
    __shared__ int sh[8];
    int lane = threadIdx.x & 31, w = threadIdx.x >> 5;
    #pragma unroll
    for (int o = 16; o > 0; o >>= 1) s += __shfl_down_sync(~0u, s, o);
    if (lane == 0) sh[w] = s;
    __syncthreads();
    if (threadIdx.x == 0) {
        int t = 0;
        #pragma unroll
        for (int j = 0; j < 8; j++) t += sh[j];
        bsum[blockIdx.y * NSB + blockIdx.x] = t;
    }
}
__global__ void k_scan3(const int* __restrict__ deg, const int* __restrict__ bsum,
                        int* __restrict__ rowptr, int* __restrict__ wptr) {
    int side = blockIdx.y;
    const int* d = deg + side * NN;
    int* rp = rowptr + side * (NN + 1);
    int* wp = wptr + side * NN;
    int lo = blockIdx.x * CHUNK, hi = min(lo + CHUNK, NN);
    __shared__ int wsum[8];
    __shared__ int srun;
    {
        int s = 0;
        for (int i = threadIdx.x; i < blockIdx.x; i += 256) s += bsum[side * NSB + i];
        int lane = threadIdx.x & 31, w = threadIdx.x >> 5;
        #pragma unroll
        for (int o = 16; o > 0; o >>= 1) s += __shfl_down_sync(~0u, s, o);
        if (lane == 0) wsum[w] = s;
        __syncthreads();
        if (threadIdx.x == 0) {
            int t = 0;
            #pragma unroll
            for (int j = 0; j < 8; j++) t += wsum[j];
            srun = t;
            if (blockIdx.x == 0) rp[NN] = EE;
        }
        __syncthreads();
    }
    int lane = threadIdx.x & 31, w = threadIdx.x >> 5;
    for (int t0 = lo; t0 < hi; t0 += 256) {
        int i = t0 + threadIdx.x;
        int v = (i < hi) ? d[i] - 1 : 0;
        int incl = v;
        #pragma unroll
        for (int o = 1; o < 32; o <<= 1) {
            int u = __shfl_up_sync(~0u, incl, o);
            if (lane >= o) incl += u;
        }
        if (lane == 31) wsum[w] = incl;
        __syncthreads();
        int woff = 0;
        for (int j = 0; j < w; j++) woff += wsum[j];
        if (i < hi) { int e = srun + woff + incl - v; rp[i] = e; wp[i] = e; }
        __syncthreads();
        if (threadIdx.x == 255) srun += woff + incl;
        __syncthreads();
    }
}
__global__ void k_fill(const int* __restrict__ es, const int* __restrict__ et,
                       int* __restrict__ wptr, int* __restrict__ csr) {
    int e = blockIdx.x * blockDim.x + threadIdx.x;
    const int* ei = blockIdx.y ? et : es;
    if (e < EE) {
        int p = atomicAdd(&wptr[blockIdx.y * NN + ei[EE + e]], 1);
        csr[blockIdx.y * EE + p] = ei[e];
    }
}

// ---------------- agg0: splits of norm-agg of raw x (128 cols) --------------
__global__ __launch_bounds__(256, 6)
void k_aggx(const float* __restrict__ xs, const float* __restrict__ xt,
            const int* __restrict__ rowptr, const int* __restrict__ csr,
            const float* __restrict__ dinv,
            __nv_bfloat16* __restrict__ oh, __nv_bfloat16* __restrict__ ol) {
    int r = blockIdx.x * 8 + threadIdx.y;
    if (r >= MT) return;
    int side = r >= MR;
    int node = r - side * MR;
    int c = threadIdx.x * 4;
    union { __nv_bfloat16 b[4]; uint2 u; } H, L;
    if (node >= NN) {
        H.u = make_uint2(0, 0);
        *(uint2*)(oh + (size_t)r * DIN + c) = H.u;
        *(uint2*)(ol + (size_t)r * DIN + c) = H.u;
        return;
    }
    const float* x = side ? xt : xs;
    const float* dv = dinv + side * NN;
    const int* rp = rowptr + side * (NN + 1);
    const int* cs = csr + side * EE;
    float di = dv[node];
    float4 v = *(const float4*)(x + (size_t)node * DIN + c);
    float w0 = di * di;
    float4 acc = make_float4(v.x*w0, v.y*w0, v.z*w0, v.w*w0);
    int lo = rp[node], hi = rp[node + 1];
    for (int e = lo; e < hi; e++) {
        int s = cs[e];
        float w = di * dv[s];
        float4 u = *(const float4*)(x + (size_t)s * DIN + c);
        acc.x += w*u.x; acc.y += w*u.y; acc.z += w*u.z; acc.w += w*u.w;
    }
    bsplit(acc.x, H.b[0], L.b[0]); bsplit(acc.y, H.b[1], L.b[1]);
    bsplit(acc.z, H.b[2], L.b[2]); bsplit(acc.w, H.b[3], L.b[3]);
    *(uint2*)(oh + (size_t)r * DIN + c) = H.u;
    *(uint2*)(ol + (size_t)r * DIN + c) = L.u;
}

// ---------------- agg1: 32 thr/node x 8 cols (2 indep loads/edge), 8 nodes --
__global__ __launch_bounds__(256, 6)
void k_aggh(const float* __restrict__ h, const int* __restrict__ rowptr,
            const int* __restrict__ csr, const float* __restrict__ dinv,
            __nv_bfloat16* __restrict__ oh, __nv_bfloat16* __restrict__ ol) {
    int r = blockIdx.x * 8 + threadIdx.y;
    if (r >= MT) return;
    int side = r >= MR;
    int node = r - side * MR;
    int c = threadIdx.x * 8;
    union { __nv_bfloat16 b[4]; uint2 u; } H, L;
    if (node >= NN) {
        H.u = make_uint2(0, 0);
        *(uint2*)(oh + (size_t)r * HH + c) = H.u;
        *(uint2*)(ol + (size_t)r * HH + c) = H.u;
        *(uint2*)(oh + (size_t)r * HH + c + 4) = H.u;
        *(uint2*)(ol + (size_t)r * HH + c + 4) = H.u;
        return;
    }
    const float* dv = dinv + side * NN;
    const int* rp = rowptr + side * (NN + 1);
    const int* cs = csr + side * EE;
    const float* hb = h + (size_t)side * MR * HH;
    float di = dv[node];
    const float* selfrow = h + (size_t)r * HH + c;
    float4 v0 = *(const float4*)selfrow;
    float4 v1 = *(const float4*)(selfrow + 4);
    float w0 = di * di;
    float4 a0 = make_float4(v0.x*w0, v0.y*w0, v0.z*w0, v0.w*w0);
    float4 a1 = make_float4(v1.x*w0, v1.y*w0, v1.z*w0, v1.w*w0);
    int lo = rp[node], hi = rp[node + 1];
    for (int e = lo; e < hi; e++) {
        int s = cs[e];
        float w = di * dv[s];
        const float* row = hb + (size_t)s * HH + c;
        float4 u0 = *(const float4*)row;
        float4 u1 = *(const float4*)(row + 4);
        a0.x += w*u0.x; a0.y += w*u0.y; a0.z += w*u0.z; a0.w += w*u0.w;
        a1.x += w*u1.x; a1.y += w*u1.y; a1.z += w*u1.z; a1.w += w*u1.w;
    }
    bsplit(a0.x, H.b[0], L.b[0]); bsplit(a0.y, H.b[1], L.b[1]);
    bsplit(a0.z, H.b[2], L.b[2]); bsplit(a0.w, H.b[3], L.b[3]);
    *(uint2*)(oh + (size_t)r * HH + c) = H.u;
    *(uint2*)(ol + (size_t)r * HH + c) = L.u;
    bsplit(a1.x, H.b[0], L.b[0]); bsplit(a1.y, H.b[1], L.b[1]);
    bsplit(a1.z, H.b[2], L.b[2]); bsplit(a1.w, H.b[3], L.b[3]);
    *(uint2*)(oh + (size_t)r * HH + c + 4) = H.u;
    *(uint2*)(ol + (size_t)r * HH + c + 4) = L.u;
}

// ---------------- bf16x3 GEMM, reg-lean pass ordering, 2 CTAs/SM ------------
template<int MODE>
__global__ __launch_bounds__(256, 2)
void k_gemm_bf(const __nv_bfloat16* __restrict__ Ah, const __nv_bfloat16* __restrict__ Al,
               const __nv_bfloat16* __restrict__ Bth, const __nv_bfloat16* __restrict__ Btl,
               const __nv_bfloat16* __restrict__ B2h, const __nv_bfloat16* __restrict__ B2l,
               const float* __restrict__ bias, float* __restrict__ Cf,
               __nv_bfloat16* __restrict__ Oh, __nv_bfloat16* __restrict__ Ol, int K) {
    extern __shared__ __nv_bfloat16 smem_dyn[];
    unsigned smb = (unsigned)__cvta_generic_to_shared(smem_dyn);
    int tid = threadIdx.x, lane = tid & 31, wid = tid >> 5;
    int wm = wid & 1, wn = wid >> 1;
    int rb = blockIdx.x * 128, cb = blockIdx.y * 128;
    int T = K >> 5;
    const __nv_bfloat16* bh_src = (MODE == 2 && rb >= MR) ? B2h : Bth;
    const __nv_bfloat16* bl_src = (MODE == 2 && rb >= MR) ? B2l : Btl;

    float acc[4][4][4];
    #pragma unroll
    for (int a = 0; a < 4; a++)
        #pragma unroll
        for (int b = 0; b < 4; b++)
            #pragma unroll
            for (int c = 0; c < 4; c++) acc[a][b][c] = 0.f;

    int srow = tid >> 1, half = tid & 1;
    const __nv_bfloat16* pa = Ah + (size_t)(rb + srow) * K + half * 16;
    const __nv_bfloat16* pl = Al + (size_t)(rb + srow) * K + half * 16;
    const __nv_bfloat16* pb = bh_src + (size_t)(cb + srow) * K + half * 16;
    const __nv_bfloat16* pq = bl_src + (size_t)(cb + srow) * K + half * 16;
    unsigned sd = (unsigned)((srow * BST + half * 16) * 2);

    auto stage = [&](int t, int buf) {
        unsigned o = smb + buf * 10240 + sd;
        CPA(o,         pa + t * 32); CPA(o + 16,    pa + t * 32 + 8);
        CPA(o + 20480, pl + t * 32); CPA(o + 20496, pl + t * 32 + 8);
        CPA(o + 40960, pb + t * 32); CPA(o + 40976, pb + t * 32 + 8);
        CPA(o + 61440, pq + t * 32); CPA(o + 61456, pq + t * 32 + 8);
    };

    stage(0, 0);
    asm volatile("cp.async.commit_group;");

    for (int t = 0; t < T; t++) {
        int buf = t & 1;
        if (t + 1 < T) {
            stage(t + 1, buf ^ 1);
            asm volatile("cp.async.commit_group;");
            asm volatile("cp.async.wait_group 1;");
        } else {
            asm volatile("cp.async.wait_group 0;");
        }
        __syncthreads();

        unsigned pAh = smb + buf * 10240;
        unsigned pAl = pAh + 20480;
        unsigned pBh = pAh + 40960;
        unsigned pBl = pAh + 61440;

        #pragma unroll
        for (int ks = 0; ks < 2; ks++) {
            unsigned ah[4][4], bf[2][4], at[4];
            int ach = ks * 2 + (lane >> 4);
            int arow = wm * 64 + (lane & 15);
            #pragma unroll
            for (int mt = 0; mt < 4; mt++)
                LDM4(ah[mt], pAh + (unsigned)(((arow + mt * 16) * BST + ach * 8) * 2));
            int bch = ks * 2 + ((lane >> 3) & 1);
            int brow = wn * 32 + (lane & 7) + (lane >> 4) * 8;
            unsigned offb0 = (unsigned)((brow * BST + bch * 8) * 2);
            unsigned offb1 = (unsigned)(((brow + 16) * BST + bch * 8) * 2);
            LDM4(bf[0], pBh + offb0);
            LDM4(bf[1], pBh + offb1);
            #pragma unroll
            for (int mt = 0; mt < 4; mt++)
                #pragma unroll
                for (int nt = 0; nt < 4; nt++)
                    MMAB(acc[mt][nt], ah[mt], bf[nt >> 1][(nt & 1) * 2], bf[nt >> 1][(nt & 1) * 2 + 1]);
            #pragma unroll
            for (int mt = 0; mt < 4; mt++) {
                LDM4(at, pAl + (unsigned)(((arow + mt * 16) * BST + ach * 8) * 2));
                #pragma unroll
                for (int nt = 0; nt < 4; nt++)
                    MMAB(acc[mt][nt], at, bf[nt >> 1][(nt & 1) * 2], bf[nt >> 1][(nt & 1) * 2 + 1]);
            }
            LDM4(bf[0], pBl + offb0);
            LDM4(bf[1], pBl + offb1);
            #pragma unroll
            for (int mt = 0; mt < 4; mt++)
                #pragma unroll
                for (int nt = 0; nt < 4; nt++)
                    MMAB(acc[mt][nt], ah[mt], bf[nt >> 1][(nt & 1) * 2], bf[nt >> 1][(nt & 1) * 2 + 1]);
        }
        __syncthreads();
    }

    int g = lane >> 2, tg = lane & 3;
    #pragma unroll
    for (int mt = 0; mt < 4; mt++) {
        int r0 = rb + wm * 64 + mt * 16 + g;
        #pragma unroll
        for (int nt = 0; nt < 4; nt++) {
            int c = cb + wn * 32 + nt * 8 + tg * 2;
            float2 bv = make_float2(0.f, 0.f);
            if (MODE < 2) bv = *(const float2*)(bias + c);
            #pragma unroll
            for (int hrow = 0; hrow < 2; hrow++) {
                int r = r0 + hrow * 8;
                float v0 = acc[mt][nt][hrow * 2];
                float v1 = acc[mt][nt][hrow * 2 + 1];
                if (MODE < 2) {
                    v0 = fmaxf(v0 + bv.x, 0.f);
                    v1 = fmaxf(v1 + bv.y, 0.f);
                }
                if (MODE == 1) {
                    __nv_bfloat16 h0, l0, h1, l1;
                    bsplit(v0, h0, l0); bsplit(v1, h1, l1);
                    *(__nv_bfloat162*)(Oh + (size_t)r * HH + c) = __nv_bfloat162(h0, h1);
                    *(__nv_bfloat162*)(Ol + (size_t)r * HH + c) = __nv_bfloat162(l0, l1);
                } else {
                    *(float2*)(Cf + (size_t)r * HH + c) = make_float2(v0, v1);
                }
            }
        }
    }
}

// ---------------- pair epilogue ---------------------------------------------
__global__ __launch_bounds__(256)
void k_pair(const float* __restrict__ Z, const int* __restrict__ y,
            const float* __restrict__ fcb, const float* __restrict__ fc2W,
            const float* __restrict__ fc2b, float* __restrict__ out) {
    int w = threadIdx.x >> 5, lane = threadIdx.x & 31;
    int p = blockIdx.x * 8 + w;
    if (p >= PP) return;
    int y0 = y[2*p], y1 = y[2*p+1];
    const float* zl = Z + (size_t)y0 * HH;
    const float* zr = Z + (size_t)(MR + y1) * HH;
    int c = lane * 8;
    float s = 0.f;
    #pragma unroll
    for (int q = 0; q < 2; q++) {
        int cc = c + q * 4;
        float4 a = *(const float4*)(zl + cc);
        float4 b = *(const float4*)(zr + cc);
        float4 fb = *(const float4*)(fcb + cc);
        float4 fw = *(const float4*)(fc2W + cc);
        s += fmaxf(a.x + b.x + fb.x, 0.f) * fw.x;
        s += fmaxf(a.y + b.y + fb.y, 0.f) * fw.y;
        s += fmaxf(a.z + b.z + fb.z, 0.f) * fw.z;
        s += fmaxf(a.w + b.w + fb.w, 0.f) * fw.w;
    }
    #pragma unroll
    for (int o = 16; o > 0; o >>= 1) s += __shfl_xor_sync(~0u, s, o);
    if (lane == 0) out[p] = 1.f / (1.f + expf(-(s + fc2b[0])));
}

// ---------------- launch ----------------------------------------------------
extern "C" void kernel_launch(void* const* d_in, const int* in_sizes, int n_in,
                              void* d_out, int out_size) {
    const float* x_s  = (const float*)d_in[0];
    const float* x_t  = (const float*)d_in[1];
    const int*   ei_s = (const int*)  d_in[2];
    const int*   ei_t = (const int*)  d_in[3];
    const int*   y    = (const int*)  d_in[4];
    const float* W1   = (const float*)d_in[5];
    const float* b1   = (const float*)d_in[6];
    const float* W2   = (const float*)d_in[7];
    const float* b2   = (const float*)d_in[8];
    const float* fcW  = (const float*)d_in[9];
    const float* fcb  = (const float*)d_in[10];
    const float* fc2W = (const float*)d_in[11];
    const float* fc2b = (const float*)d_in[12];
    float* out = (float*)d_out;

    float *h, *dv;
    __nv_bfloat16 *Ah, *Al, *Ch, *Cl, *Bh, *Bl;
    int *deg, *rp, *wp, *cs, *bs;
    cudaGetSymbolAddress((void**)&h,  g_h);
    cudaGetSymbolAddress((void**)&Ah, g_Ah);
    cudaGetSymbolAddress((void**)&Al, g_Al);
    cudaGetSymbolAddress((void**)&Ch, g_Ch);
    cudaGetSymbolAddress((void**)&Cl, g_Cl);
    cudaGetSymbolAddress((void**)&Bh, g_Bh);
    cudaGetSymbolAddress((void**)&Bl, g_Bl);
    cudaGetSymbolAddress((void**)&dv, g_dinv);
    cudaGetSymbolAddress((void**)&deg, g_deg);
    cudaGetSymbolAddress((void**)&rp, g_rowptr);
    cudaGetSymbolAddress((void**)&wp, g_wptr);
    cudaGetSymbolAddress((void**)&cs, g_csr);
    cudaGetSymbolAddress((void**)&bs, g_bsum);

    cudaFuncSetAttribute(k_gemm_bf<0>, cudaFuncAttributeMaxDynamicSharedMemorySize, 81920);
    cudaFuncSetAttribute(k_gemm_bf<1>, cudaFuncAttributeMaxDynamicSharedMemorySize, 81920);
    cudaFuncSetAttribute(k_gemm_bf<2>, cudaFuncAttributeMaxDynamicSharedMemorySize, 81920);

    k_prep<<<615, 256>>>(W1, W2, fcW, Bh, Bl, deg);

    dim3 ge((EE + 255) / 256, 2);
    k_count<<<ge, 256>>>(ei_s, ei_t, deg);
    k_scan1<<<dim3(NSB, 2), 256>>>(deg, bs, dv);
    k_scan3<<<dim3(NSB, 2), 256>>>(deg, bs, rp, wp);
    k_fill<<<ge, 256>>>(ei_s, ei_t, wp, cs);

    dim3 gg(MT / 128, 2);
    k_aggx<<<MT / 8, dim3(32, 8)>>>(x_s, x_t, rp, cs, dv, Ah, Al);
    k_gemm_bf<0><<<gg, 256, 81920>>>(Ah, Al, Bh, Bl, Bh, Bl, b1, h, Ah, Al, DIN);
    k_aggh<<<MT / 8, dim3(32, 8)>>>(h, rp, cs, dv, Ch, Cl);
    k_gemm_bf<1><<<gg, 256, 81920>>>(Ch, Cl, Bh + 32768, Bl + 32768, Bh, Bl, b2, h, Ah, Al, HH);
    k_gemm_bf<2><<<gg, 256, 81920>>>(Ah, Al, Bh + 98304, Bl + 98304, Bh + 163840, Bl + 163840,
                                     b2, h, Ah, Al, HH);
    k_pair<<<(PP + 7) / 8, 256>>>(h, y, fcb, fc2W, fc2b, out);
}